// round 7
// baseline (speedup 1.0000x reference)
#include <cuda_runtime.h>

#define MAXN 50000
#define MAXE 800000
#define DINC 128
#define DHC  128
#define DOUTC 64

// ---- scratch (static device globals; no allocation allowed) ----
__device__ int   g_deg[MAXN];
__device__ float g_dinv[MAXN];
__device__ int   g_offs[MAXN + 1];
__device__ int   g_cursor[MAXN];
__device__ int2  g_bpair[MAXE];          // (src, original edge id), bucketed by dst
__device__ float g_xw1[MAXN * DHC];
__device__ float g_h1 [MAXN * DHC];
__device__ float g_xw2[MAXN * DOUTC];
__device__ float g_h2 [MAXN * DOUTC];

// ---------------- small helpers ----------------
__device__ __forceinline__ float4 f4fma(float4 a, float s, float4 acc) {
    acc.x += a.x * s; acc.y += a.y * s; acc.z += a.z * s; acc.w += a.w * s;
    return acc;
}

// ---------------- degree (1 edge/thread — measured best) ----------------
__global__ void k_deg(const int* __restrict__ dst, int* deg, int E) {
    int e = blockIdx.x * blockDim.x + threadIdx.x;
    if (e < E) atomicAdd(&deg[dst[e]], 1);
}

// ---------------- fused scan: offs (exclusive), cursor copy, dinv ----------------
__global__ void k_scan(const int* __restrict__ deg, int* __restrict__ offs,
                       int* __restrict__ cursor, float* __restrict__ dinv, int n) {
    const int T = 1024;
    __shared__ int s[T];
    int tid = threadIdx.x;
    int per = (n + T - 1) / T;
    int start = tid * per;
    int sum = 0;
    for (int i = 0; i < per; i++) {
        int idx = start + i;
        if (idx < n) sum += deg[idx];
    }
    s[tid] = sum;
    __syncthreads();
    for (int d = 1; d < T; d <<= 1) {
        int v = 0;
        if (tid >= d) v = s[tid - d];
        __syncthreads();
        if (tid >= d) s[tid] += v;
        __syncthreads();
    }
    int run = s[tid] - sum;
    for (int i = 0; i < per; i++) {
        int idx = start + i;
        if (idx < n) {
            int dg = deg[idx];
            offs[idx] = run;
            cursor[idx] = run;
            dinv[idx] = rsqrtf((float)(dg + 1));  // +1 self-loop
            run += dg;
        }
    }
    if (tid == T - 1) offs[n] = run;
}

// ---------------- bucket edges by dst, storing (src, edge id) ----------------
__global__ void k_bucket(const int* __restrict__ src, const int* __restrict__ dst,
                         int* cursor, int2* __restrict__ bpair, int E) {
    int e = blockIdx.x * blockDim.x + threadIdx.x;
    if (e >= E) return;
    int d = dst[e];
    int p = atomicAdd(&cursor[d], 1);
    bpair[p] = make_int2(src[e], e);
}

// ---------------- GEMM: out[n,NCOL] = act(X[n,128]) @ W[128,NCOL] ----------------
template <int NCOL, bool RELU_IN>
__global__ __launch_bounds__(256) void k_gemm(const float* __restrict__ X,
                                              const float* __restrict__ W,
                                              float* __restrict__ out, int n) {
    constexpr int KT = 16;
    constexpr int COLG = NCOL / 4;
    constexpr int RTH = 256 / COLG;
    constexpr int RPT = 64 / RTH;
    __shared__ float Xs[KT][68];
    __shared__ float Ws[KT][NCOL];

    int tid = threadIdx.x;
    int row0 = blockIdx.x * 64;
    int cx = tid % COLG;
    int ry = tid / COLG;

    float4 acc[RPT];
#pragma unroll
    for (int j = 0; j < RPT; j++) acc[j] = make_float4(0.f, 0.f, 0.f, 0.f);

    for (int k0 = 0; k0 < 128; k0 += KT) {
        __syncthreads();
        {
            int rr = tid >> 2;
            int kv = (tid & 3) * 4;
            int row = row0 + rr;
            float4 v = make_float4(0.f, 0.f, 0.f, 0.f);
            if (row < n) v = __ldg(reinterpret_cast<const float4*>(X + row * 128 + k0 + kv));
            if (RELU_IN) {
                v.x = fmaxf(v.x, 0.f); v.y = fmaxf(v.y, 0.f);
                v.z = fmaxf(v.z, 0.f); v.w = fmaxf(v.w, 0.f);
            }
            Xs[kv + 0][rr] = v.x; Xs[kv + 1][rr] = v.y;
            Xs[kv + 2][rr] = v.z; Xs[kv + 3][rr] = v.w;
        }
#pragma unroll
        for (int lin = tid; lin < KT * COLG; lin += 256) {
            int kk = lin / COLG;
            int c = lin % COLG;
            *reinterpret_cast<float4*>(&Ws[kk][c * 4]) =
                __ldg(reinterpret_cast<const float4*>(W + (k0 + kk) * NCOL + c * 4));
        }
        __syncthreads();
#pragma unroll
        for (int kk = 0; kk < KT; kk++) {
            float4 w = *reinterpret_cast<float4*>(&Ws[kk][cx * 4]);
#pragma unroll
            for (int rv = 0; rv < RPT / 4; rv++) {
                float4 xr = *reinterpret_cast<float4*>(&Xs[kk][ry * RPT + rv * 4]);
                acc[rv * 4 + 0] = f4fma(w, xr.x, acc[rv * 4 + 0]);
                acc[rv * 4 + 1] = f4fma(w, xr.y, acc[rv * 4 + 1]);
                acc[rv * 4 + 2] = f4fma(w, xr.z, acc[rv * 4 + 2]);
                acc[rv * 4 + 3] = f4fma(w, xr.w, acc[rv * 4 + 3]);
            }
        }
    }
#pragma unroll
    for (int j = 0; j < RPT; j++) {
        int row = row0 + ry * RPT + j;
        if (row < n)
            *reinterpret_cast<float4*>(out + (size_t)row * NCOL + cx * 4) = acc[j];
    }
}

// ---------------- gather aggregation, d=128: warp/node, 2-wide unroll (measured best) ----------------
__global__ __launch_bounds__(256) void k_agg128(
    const float4* __restrict__ xw, const int* __restrict__ offs,
    const int2* __restrict__ bpair, const float* __restrict__ dinv,
    const float4* __restrict__ bias, float4* __restrict__ h, int n) {
    int t = blockIdx.x * blockDim.x + threadIdx.x;
    int node = t >> 5;
    int lane = t & 31;
    if (node >= n) return;
    float dn = __ldg(dinv + node);
    float4 bb = __ldg(bias + lane);
    float4 acc = f4fma(__ldg(xw + (size_t)node * 32 + lane), dn * dn, bb);
    int beg = __ldg(offs + node), end = __ldg(offs + node + 1);
    int j = beg;
    for (; j + 1 < end; j += 2) {
        int s0 = __ldg(&bpair[j].x), s1 = __ldg(&bpair[j + 1].x);
        float n0 = __ldg(dinv + s0) * dn, n1 = __ldg(dinv + s1) * dn;
        float4 v0 = __ldg(xw + (size_t)s0 * 32 + lane);
        float4 v1 = __ldg(xw + (size_t)s1 * 32 + lane);
        acc = f4fma(v0, n0, acc);
        acc = f4fma(v1, n1, acc);
    }
    if (j < end) {
        int s0 = __ldg(&bpair[j].x);
        acc = f4fma(__ldg(xw + (size_t)s0 * 32 + lane), __ldg(dinv + s0) * dn, acc);
    }
    h[(size_t)node * 32 + lane] = acc;
}

// ---------------- gather aggregation, d=64: warp/node, 2-wide unroll ----------------
__global__ __launch_bounds__(256) void k_agg64(
    const float2* __restrict__ xw, const int* __restrict__ offs,
    const int2* __restrict__ bpair, const float* __restrict__ dinv,
    const float2* __restrict__ bias, float2* __restrict__ h, int n) {
    int t = blockIdx.x * blockDim.x + threadIdx.x;
    int node = t >> 5;
    int lane = t & 31;
    if (node >= n) return;
    float dn = __ldg(dinv + node);
    float2 bb = __ldg(bias + lane);
    float2 v0 = __ldg(xw + (size_t)node * 32 + lane);
    float s = dn * dn;
    float2 acc = make_float2(v0.x * s + bb.x, v0.y * s + bb.y);
    int beg = __ldg(offs + node), end = __ldg(offs + node + 1);
    int j = beg;
    for (; j + 1 < end; j += 2) {
        int s0 = __ldg(&bpair[j].x), s1 = __ldg(&bpair[j + 1].x);
        float n0 = __ldg(dinv + s0) * dn, n1 = __ldg(dinv + s1) * dn;
        float2 a = __ldg(xw + (size_t)s0 * 32 + lane);
        float2 b = __ldg(xw + (size_t)s1 * 32 + lane);
        acc.x += a.x * n0 + b.x * n1;
        acc.y += a.y * n0 + b.y * n1;
    }
    if (j < end) {
        int s0 = __ldg(&bpair[j].x);
        float n0 = __ldg(dinv + s0) * dn;
        float2 a = __ldg(xw + (size_t)s0 * 32 + lane);
        acc.x += a.x * n0; acc.y += a.y * n0;
    }
    h[(size_t)node * 32 + lane] = acc;
}

// ---------------- edge scorer, CSR form: warp per dst node, dst row cached in regs ----------------
// score[eid] = dot(h2[src], h2[dst]); per edge only the src row (256B) is gathered.
__global__ __launch_bounds__(256) void k_score(
    const float2* __restrict__ h2, const int* __restrict__ offs,
    const int2* __restrict__ bpair, float* __restrict__ out, int n) {
    int t = blockIdx.x * blockDim.x + threadIdx.x;
    int node = t >> 5;
    int lane = t & 31;
    if (node >= n) return;
    float2 hd = __ldg(h2 + (size_t)node * 32 + lane);  // dst row held in registers
    int beg = __ldg(offs + node), end = __ldg(offs + node + 1);
    int j = beg;
    for (; j + 1 < end; j += 2) {
        int2 e0 = __ldg(bpair + j);
        int2 e1 = __ldg(bpair + j + 1);
        float2 a0 = __ldg(h2 + (size_t)e0.x * 32 + lane);
        float2 a1 = __ldg(h2 + (size_t)e1.x * 32 + lane);
        float p0 = a0.x * hd.x + a0.y * hd.y;
        float p1 = a1.x * hd.x + a1.y * hd.y;
#pragma unroll
        for (int off = 16; off; off >>= 1) {
            p0 += __shfl_xor_sync(0xFFFFFFFFu, p0, off);
            p1 += __shfl_xor_sync(0xFFFFFFFFu, p1, off);
        }
        if (lane == 0) { out[e0.y] = p0; out[e1.y] = p1; }
    }
    if (j < end) {
        int2 e0 = __ldg(bpair + j);
        float2 a0 = __ldg(h2 + (size_t)e0.x * 32 + lane);
        float p0 = a0.x * hd.x + a0.y * hd.y;
#pragma unroll
        for (int off = 16; off; off >>= 1) p0 += __shfl_xor_sync(0xFFFFFFFFu, p0, off);
        if (lane == 0) out[e0.y] = p0;
    }
}

static inline int cdiv(long long a, int b) { return (int)((a + b - 1) / b); }

extern "C" void kernel_launch(void* const* d_in, const int* in_sizes, int n_in,
                              void* d_out, int out_size) {
    const float* x   = (const float*)d_in[0];
    const int*   src = (const int*)  d_in[1];
    const int*   dst = (const int*)  d_in[2];
    const float* W1  = (const float*)d_in[3];
    const float* b1  = (const float*)d_in[4];
    const float* W2  = (const float*)d_in[5];
    const float* b2  = (const float*)d_in[6];
    float* score = (float*)d_out;

    int n = in_sizes[0] / DINC;
    int E = in_sizes[1];

    void *p_deg, *p_dinv, *p_offs, *p_cursor, *p_bpair, *p_xw1, *p_h1, *p_xw2, *p_h2;
    cudaGetSymbolAddress(&p_deg,    g_deg);
    cudaGetSymbolAddress(&p_dinv,   g_dinv);
    cudaGetSymbolAddress(&p_offs,   g_offs);
    cudaGetSymbolAddress(&p_cursor, g_cursor);
    cudaGetSymbolAddress(&p_bpair,  g_bpair);
    cudaGetSymbolAddress(&p_xw1,    g_xw1);
    cudaGetSymbolAddress(&p_h1,     g_h1);
    cudaGetSymbolAddress(&p_xw2,    g_xw2);
    cudaGetSymbolAddress(&p_h2,     g_h2);
    int*   deg    = (int*)p_deg;
    float* dinv   = (float*)p_dinv;
    int*   offs   = (int*)p_offs;
    int*   cursor = (int*)p_cursor;
    int2*  bpair  = (int2*)p_bpair;
    float* xw1    = (float*)p_xw1;
    float* h1     = (float*)p_h1;
    float* xw2    = (float*)p_xw2;
    float* h2     = (float*)p_h2;

    const int B = 256;

    // ---- CSR build ----
    cudaMemsetAsync(deg, 0, (size_t)n * sizeof(int));
    k_deg<<<cdiv(E, B), B>>>(dst, deg, E);
    k_scan<<<1, 1024>>>(deg, offs, cursor, dinv, n);
    k_bucket<<<cdiv(E, B), B>>>(src, dst, cursor, bpair, E);

    // ---- layer 1 ----
    k_gemm<DHC, false><<<cdiv(n, 64), B>>>(x, W1, xw1, n);
    k_agg128<<<cdiv((long long)n * 32, B), B>>>((const float4*)xw1, offs, bpair, dinv,
                                                (const float4*)b1, (float4*)h1, n);

    // ---- layer 2 (relu fused into GEMM input) ----
    k_gemm<DOUTC, true><<<cdiv(n, 64), B>>>(h1, W2, xw2, n);
    k_agg64<<<cdiv((long long)n * 32, B), B>>>((const float2*)xw2, offs, bpair, dinv,
                                               (const float2*)b2, (float2*)h2, n);

    // ---- edge scores: CSR order, dst row cached per warp ----
    k_score<<<cdiv((long long)n * 32, B), B>>>((const float2*)h2, offs, bpair, score, n);
}

// round 8
// speedup vs baseline: 1.3772x; 1.3772x over previous
#include <cuda_runtime.h>
#include <mma.h>

using namespace nvcuda;

#define MAXN 50000
#define MAXE 800000
#define DINC 128
#define DHC  128
#define DOUTC 64

// ---- scratch (static device globals; no allocation allowed) ----
__device__ int   g_deg[MAXN];
__device__ float g_dinv[MAXN];
__device__ int   g_offs[MAXN + 1];
__device__ int   g_cursor[MAXN];
__device__ int   g_bsrc[MAXE];
__device__ float g_xw1[MAXN * DHC];
__device__ float g_h1 [MAXN * DHC];
__device__ float g_xw2[MAXN * DOUTC];
__device__ float g_h2 [MAXN * DOUTC];

// ---------------- small helpers ----------------
__device__ __forceinline__ float4 f4fma(float4 a, float s, float4 acc) {
    acc.x += a.x * s; acc.y += a.y * s; acc.z += a.z * s; acc.w += a.w * s;
    return acc;
}

// ---------------- degree (1 edge/thread — measured best) ----------------
__global__ void k_deg(const int* __restrict__ dst, int* deg, int E) {
    int e = blockIdx.x * blockDim.x + threadIdx.x;
    if (e < E) atomicAdd(&deg[dst[e]], 1);
}

// ---------------- fused scan: offs (exclusive), cursor copy, dinv ----------------
__global__ void k_scan(const int* __restrict__ deg, int* __restrict__ offs,
                       int* __restrict__ cursor, float* __restrict__ dinv, int n) {
    const int T = 1024;
    __shared__ int s[T];
    int tid = threadIdx.x;
    int per = (n + T - 1) / T;
    int start = tid * per;
    int sum = 0;
    for (int i = 0; i < per; i++) {
        int idx = start + i;
        if (idx < n) sum += deg[idx];
    }
    s[tid] = sum;
    __syncthreads();
    for (int d = 1; d < T; d <<= 1) {
        int v = 0;
        if (tid >= d) v = s[tid - d];
        __syncthreads();
        if (tid >= d) s[tid] += v;
        __syncthreads();
    }
    int run = s[tid] - sum;
    for (int i = 0; i < per; i++) {
        int idx = start + i;
        if (idx < n) {
            int dg = deg[idx];
            offs[idx] = run;
            cursor[idx] = run;
            dinv[idx] = rsqrtf((float)(dg + 1));  // +1 self-loop
            run += dg;
        }
    }
    if (tid == T - 1) offs[n] = run;
}

// ---------------- bucket edges by dst (1 edge/thread — measured best) ----------------
__global__ void k_bucket(const int* __restrict__ src, const int* __restrict__ dst,
                         int* cursor, int* __restrict__ bsrc, int E) {
    int e = blockIdx.x * blockDim.x + threadIdx.x;
    if (e >= E) return;
    int d = dst[e];
    int p = atomicAdd(&cursor[d], 1);
    bsrc[p] = src[e];
}

// ---------------- GEMM via tf32 tensor cores: out[n,NCOL] = X[n,128] @ W[128,NCOL] ----------------
// 64 rows/block, 8 warps: 4 row-groups x 2 col-groups. Fragments loaded straight from gmem
// (W is 64/32 KB -> L1/L2 resident; X rows read once per col-group). Tail tile scalar.
template <int NCOL>
__global__ __launch_bounds__(256) void k_gemm_tc(const float* __restrict__ X,
                                                 const float* __restrict__ W,
                                                 float* __restrict__ out, int n) {
    constexpr int CPW = (NCOL == 128) ? 64 : 32;  // cols per warp
    constexpr int NF = CPW / 16;                  // b/c frags per warp
    int wid = threadIdx.x >> 5;
    int r = wid & 3;   // row group 0..3 (16 rows each)
    int c = wid >> 2;  // col group 0..1
    int row0 = blockIdx.x * 64;

    if (row0 + 64 <= n) {
        wmma::fragment<wmma::matrix_a, 16, 16, 8, wmma::precision::tf32, wmma::row_major> fa;
        wmma::fragment<wmma::matrix_b, 16, 16, 8, wmma::precision::tf32, wmma::row_major> fb;
        wmma::fragment<wmma::accumulator, 16, 16, 8, float> fc[NF];
#pragma unroll
        for (int f = 0; f < NF; f++) wmma::fill_fragment(fc[f], 0.f);
        const float* arow = X + (size_t)(row0 + r * 16) * 128;
#pragma unroll
        for (int k0 = 0; k0 < 128; k0 += 8) {
            wmma::load_matrix_sync(fa, arow + k0, 128);
#pragma unroll
            for (int i = 0; i < fa.num_elements; i++) fa.x[i] = wmma::__float_to_tf32(fa.x[i]);
#pragma unroll
            for (int f = 0; f < NF; f++) {
                wmma::load_matrix_sync(fb, W + (size_t)k0 * NCOL + c * CPW + f * 16, NCOL);
#pragma unroll
                for (int i = 0; i < fb.num_elements; i++) fb.x[i] = wmma::__float_to_tf32(fb.x[i]);
                wmma::mma_sync(fc[f], fa, fb, fc[f]);
            }
        }
#pragma unroll
        for (int f = 0; f < NF; f++)
            wmma::store_matrix_sync(out + (size_t)(row0 + r * 16) * NCOL + c * CPW + f * 16,
                                    fc[f], NCOL, wmma::mem_row_major);
    } else {
        // partial tail tile (16 rows for n=50000): scalar fp32 path
        int tid = threadIdx.x;
        int rows = n - row0;
        for (int idx = tid; idx < rows * NCOL; idx += 256) {
            int rr = idx / NCOL, cc = idx % NCOL;
            const float* xr = X + (size_t)(row0 + rr) * 128;
            float s = 0.f;
            for (int k = 0; k < 128; k++) s += xr[k] * __ldg(W + k * NCOL + cc);
            out[(size_t)(row0 + rr) * NCOL + cc] = s;
        }
    }
}

// ---------------- gather aggregation, d=128: warp/node, 2-wide unroll; relu epilogue ----------------
__global__ __launch_bounds__(256) void k_agg128(
    const float4* __restrict__ xw, const int* __restrict__ offs,
    const int* __restrict__ bsrc, const float* __restrict__ dinv,
    const float4* __restrict__ bias, float4* __restrict__ h, int n) {
    int t = blockIdx.x * blockDim.x + threadIdx.x;
    int node = t >> 5;
    int lane = t & 31;
    if (node >= n) return;
    float dn = __ldg(dinv + node);
    float4 bb = __ldg(bias + lane);
    float4 acc = f4fma(__ldg(xw + (size_t)node * 32 + lane), dn * dn, bb);
    int beg = __ldg(offs + node), end = __ldg(offs + node + 1);
    int j = beg;
    for (; j + 1 < end; j += 2) {
        int s0 = __ldg(bsrc + j), s1 = __ldg(bsrc + j + 1);
        float n0 = __ldg(dinv + s0) * dn, n1 = __ldg(dinv + s1) * dn;
        float4 v0 = __ldg(xw + (size_t)s0 * 32 + lane);
        float4 v1 = __ldg(xw + (size_t)s1 * 32 + lane);
        acc = f4fma(v0, n0, acc);
        acc = f4fma(v1, n1, acc);
    }
    if (j < end) {
        int s0 = __ldg(bsrc + j);
        acc = f4fma(__ldg(xw + (size_t)s0 * 32 + lane), __ldg(dinv + s0) * dn, acc);
    }
    // relu fused here (h1 feeds only GEMM2)
    acc.x = fmaxf(acc.x, 0.f); acc.y = fmaxf(acc.y, 0.f);
    acc.z = fmaxf(acc.z, 0.f); acc.w = fmaxf(acc.w, 0.f);
    h[(size_t)node * 32 + lane] = acc;
}

// ---------------- gather aggregation, d=64: warp/node, 2-wide unroll ----------------
__global__ __launch_bounds__(256) void k_agg64(
    const float2* __restrict__ xw, const int* __restrict__ offs,
    const int* __restrict__ bsrc, const float* __restrict__ dinv,
    const float2* __restrict__ bias, float2* __restrict__ h, int n) {
    int t = blockIdx.x * blockDim.x + threadIdx.x;
    int node = t >> 5;
    int lane = t & 31;
    if (node >= n) return;
    float dn = __ldg(dinv + node);
    float2 bb = __ldg(bias + lane);
    float2 v0 = __ldg(xw + (size_t)node * 32 + lane);
    float s = dn * dn;
    float2 acc = make_float2(v0.x * s + bb.x, v0.y * s + bb.y);
    int beg = __ldg(offs + node), end = __ldg(offs + node + 1);
    int j = beg;
    for (; j + 1 < end; j += 2) {
        int s0 = __ldg(bsrc + j), s1 = __ldg(bsrc + j + 1);
        float n0 = __ldg(dinv + s0) * dn, n1 = __ldg(dinv + s1) * dn;
        float2 a = __ldg(xw + (size_t)s0 * 32 + lane);
        float2 b = __ldg(xw + (size_t)s1 * 32 + lane);
        acc.x += a.x * n0 + b.x * n1;
        acc.y += a.y * n0 + b.y * n1;
    }
    if (j < end) {
        int s0 = __ldg(bsrc + j);
        float n0 = __ldg(dinv + s0) * dn;
        float2 a = __ldg(xw + (size_t)s0 * 32 + lane);
        acc.x += a.x * n0; acc.y += a.y * n0;
    }
    h[(size_t)node * 32 + lane] = acc;
}

// ---------------- edge scorer (flat, 16 lanes/edge — measured best) ----------------
__global__ __launch_bounds__(256) void k_score(const float4* __restrict__ h2,
                                               const int* __restrict__ src,
                                               const int* __restrict__ dst,
                                               float* __restrict__ out, int E) {
    int t = blockIdx.x * blockDim.x + threadIdx.x;
    int e = t >> 4;
    int lane = t & 15;
    if (e >= E) return;
    int s = __ldg(src + e);
    int d = __ldg(dst + e);
    float4 a = __ldg(h2 + (size_t)s * 16 + lane);
    float4 b = __ldg(h2 + (size_t)d * 16 + lane);
    float p = a.x * b.x + a.y * b.y + a.z * b.z + a.w * b.w;
#pragma unroll
    for (int off = 8; off; off >>= 1) p += __shfl_xor_sync(0xFFFFFFFFu, p, off);
    if (lane == 0) out[e] = p;
}

static inline int cdiv(long long a, int b) { return (int)((a + b - 1) / b); }

extern "C" void kernel_launch(void* const* d_in, const int* in_sizes, int n_in,
                              void* d_out, int out_size) {
    const float* x   = (const float*)d_in[0];
    const int*   src = (const int*)  d_in[1];
    const int*   dst = (const int*)  d_in[2];
    const float* W1  = (const float*)d_in[3];
    const float* b1  = (const float*)d_in[4];
    const float* W2  = (const float*)d_in[5];
    const float* b2  = (const float*)d_in[6];
    float* score = (float*)d_out;

    int n = in_sizes[0] / DINC;
    int E = in_sizes[1];

    void *p_deg, *p_dinv, *p_offs, *p_cursor, *p_bsrc, *p_xw1, *p_h1, *p_xw2, *p_h2;
    cudaGetSymbolAddress(&p_deg,    g_deg);
    cudaGetSymbolAddress(&p_dinv,   g_dinv);
    cudaGetSymbolAddress(&p_offs,   g_offs);
    cudaGetSymbolAddress(&p_cursor, g_cursor);
    cudaGetSymbolAddress(&p_bsrc,   g_bsrc);
    cudaGetSymbolAddress(&p_xw1,    g_xw1);
    cudaGetSymbolAddress(&p_h1,     g_h1);
    cudaGetSymbolAddress(&p_xw2,    g_xw2);
    cudaGetSymbolAddress(&p_h2,     g_h2);
    int*   deg    = (int*)p_deg;
    float* dinv   = (float*)p_dinv;
    int*   offs   = (int*)p_offs;
    int*   cursor = (int*)p_cursor;
    int*   bsrc   = (int*)p_bsrc;
    float* xw1    = (float*)p_xw1;
    float* h1     = (float*)p_h1;
    float* xw2    = (float*)p_xw2;
    float* h2     = (float*)p_h2;

    const int B = 256;

    // ---- CSR build ----
    cudaMemsetAsync(deg, 0, (size_t)n * sizeof(int));
    k_deg<<<cdiv(E, B), B>>>(dst, deg, E);
    k_scan<<<1, 1024>>>(deg, offs, cursor, dinv, n);
    k_bucket<<<cdiv(E, B), B>>>(src, dst, cursor, bsrc, E);

    // ---- layer 1 (tf32 tensor GEMM) ----
    k_gemm_tc<DHC><<<cdiv(n, 64), B>>>(x, W1, xw1, n);
    k_agg128<<<cdiv((long long)n * 32, B), B>>>((const float4*)xw1, offs, bsrc, dinv,
                                                (const float4*)b1, (float4*)h1, n);

    // ---- layer 2 (relu applied in agg128 epilogue; tf32 tensor GEMM) ----
    k_gemm_tc<DOUTC><<<cdiv(n, 64), B>>>(h1, W2, xw2, n);
    k_agg64<<<cdiv((long long)n * 32, B), B>>>((const float2*)xw2, offs, bsrc, dinv,
                                               (const float2*)b2, (float2*)h2, n);

    // ---- edge scores ----
    k_score<<<cdiv((long long)E * 16, B), B>>>((const float4*)h2, src, dst, score, E);
}

// round 9
// speedup vs baseline: 1.5139x; 1.0993x over previous
#include <cuda_runtime.h>
#include <mma.h>

using namespace nvcuda;

#define MAXN 50000
#define NPAD 50048            // 391 * 128: wmma tiles write full 128-row tiles
#define MAXE 800000
#define DINC 128
#define DHC  128
#define DOUTC 64

// ---- scratch (static device globals; no allocation allowed) ----
__device__ int   g_deg[MAXN];
__device__ float g_dinv[MAXN];
__device__ int   g_offs[MAXN + 1];
__device__ int   g_cursor[MAXN];
__device__ int   g_bsrc[MAXE];
__device__ float g_xw1[NPAD * DHC];
__device__ float g_h1 [NPAD * DHC];
__device__ float g_xw2[NPAD * DOUTC];
__device__ float g_h2 [NPAD * DOUTC];

// ---------------- small helpers ----------------
__device__ __forceinline__ float4 f4fma(float4 a, float s, float4 acc) {
    acc.x += a.x * s; acc.y += a.y * s; acc.z += a.z * s; acc.w += a.w * s;
    return acc;
}

// ---------------- degree (1 edge/thread — measured best) ----------------
__global__ void k_deg(const int* __restrict__ dst, int* deg, int E) {
    int e = blockIdx.x * blockDim.x + threadIdx.x;
    if (e < E) atomicAdd(&deg[dst[e]], 1);
}

// ---------------- fused scan: offs (exclusive), cursor copy, dinv ----------------
__global__ void k_scan(const int* __restrict__ deg, int* __restrict__ offs,
                       int* __restrict__ cursor, float* __restrict__ dinv, int n) {
    const int T = 1024;
    __shared__ int s[T];
    int tid = threadIdx.x;
    int per = (n + T - 1) / T;
    int start = tid * per;
    int sum = 0;
    for (int i = 0; i < per; i++) {
        int idx = start + i;
        if (idx < n) sum += deg[idx];
    }
    s[tid] = sum;
    __syncthreads();
    for (int d = 1; d < T; d <<= 1) {
        int v = 0;
        if (tid >= d) v = s[tid - d];
        __syncthreads();
        if (tid >= d) s[tid] += v;
        __syncthreads();
    }
    int run = s[tid] - sum;
    for (int i = 0; i < per; i++) {
        int idx = start + i;
        if (idx < n) {
            int dg = deg[idx];
            offs[idx] = run;
            cursor[idx] = run;
            dinv[idx] = rsqrtf((float)(dg + 1));  // +1 self-loop
            run += dg;
        }
    }
    if (tid == T - 1) offs[n] = run;
}

// ---------------- bucket edges by dst (1 edge/thread — measured best) ----------------
__global__ void k_bucket(const int* __restrict__ src, const int* __restrict__ dst,
                         int* cursor, int* __restrict__ bsrc, int E) {
    int e = blockIdx.x * blockDim.x + threadIdx.x;
    if (e >= E) return;
    int d = dst[e];
    int p = atomicAdd(&cursor[d], 1);
    bsrc[p] = src[e];
}

// ---------------- tf32 wmma GEMM, SMEM-staged: out[NPADrows,NCOL] = act(X) @ W ----------------
// 128-row tile, 256 threads = 8 warps in 4 (row) x 2 (col) grid. Warp tile: 32 x NCOL/2.
// Zero-filled staging for rows >= n; out is padded so full-tile stores are safe.
template <int NCOL, bool RELU_IN>
__global__ __launch_bounds__(256) void k_gemm_tc(const float* __restrict__ X,
                                                 const float* __restrict__ W,
                                                 float* __restrict__ out, int n) {
    constexpr int NB = NCOL / 32;        // b-frags per warp (4 or 2)
    constexpr int XP = 20;               // padded X row (mult of 4 for ldm)
    __shared__ float Xs[128][XP];
    __shared__ float Ws[16][NCOL];

    int tid = threadIdx.x;
    int wid = tid >> 5;
    int rg = wid & 3;                    // row group: rows rg*32
    int cg = wid >> 2;                   // col group: cols cg*NCOL/2
    int row0 = blockIdx.x * 128;

    wmma::fragment<wmma::matrix_a, 16, 16, 8, wmma::precision::tf32, wmma::row_major> fa0, fa1;
    wmma::fragment<wmma::matrix_b, 16, 16, 8, wmma::precision::tf32, wmma::row_major> fb;
    wmma::fragment<wmma::accumulator, 16, 16, 8, float> acc[2][NB];
#pragma unroll
    for (int i = 0; i < 2; i++)
#pragma unroll
        for (int f = 0; f < NB; f++) wmma::fill_fragment(acc[i][f], 0.f);

    for (int k0 = 0; k0 < 128; k0 += 16) {
        __syncthreads();
        // stage X tile: 128 rows x 16 k (zero-fill rows >= n)
#pragma unroll
        for (int p = 0; p < 2; p++) {
            int lin = tid + p * 256;        // 0..511
            int row = lin >> 2;
            int c4 = (lin & 3) * 4;
            int grow = row0 + row;
            float4 v = make_float4(0.f, 0.f, 0.f, 0.f);
            if (grow < n) v = __ldg(reinterpret_cast<const float4*>(X + (size_t)grow * 128 + k0 + c4));
            if (RELU_IN) {
                v.x = fmaxf(v.x, 0.f); v.y = fmaxf(v.y, 0.f);
                v.z = fmaxf(v.z, 0.f); v.w = fmaxf(v.w, 0.f);
            }
            *reinterpret_cast<float4*>(&Xs[row][c4]) = v;
        }
        // stage W tile: 16 x NCOL
#pragma unroll
        for (int lin = tid; lin < 16 * NCOL / 4; lin += 256) {
            int row = lin / (NCOL / 4);
            int c4 = (lin % (NCOL / 4)) * 4;
            *reinterpret_cast<float4*>(&Ws[row][c4]) =
                __ldg(reinterpret_cast<const float4*>(W + (size_t)(k0 + row) * NCOL + c4));
        }
        __syncthreads();
#pragma unroll
        for (int ks = 0; ks < 16; ks += 8) {
            wmma::load_matrix_sync(fa0, &Xs[rg * 32 + 0][ks], XP);
            wmma::load_matrix_sync(fa1, &Xs[rg * 32 + 16][ks], XP);
#pragma unroll
            for (int i = 0; i < fa0.num_elements; i++) {
                fa0.x[i] = wmma::__float_to_tf32(fa0.x[i]);
                fa1.x[i] = wmma::__float_to_tf32(fa1.x[i]);
            }
#pragma unroll
            for (int f = 0; f < NB; f++) {
                wmma::load_matrix_sync(fb, &Ws[ks][cg * (NCOL / 2) + f * 16], NCOL);
#pragma unroll
                for (int i = 0; i < fb.num_elements; i++) fb.x[i] = wmma::__float_to_tf32(fb.x[i]);
                wmma::mma_sync(acc[0][f], fa0, fb, acc[0][f]);
                wmma::mma_sync(acc[1][f], fa1, fb, acc[1][f]);
            }
        }
    }
#pragma unroll
    for (int i = 0; i < 2; i++)
#pragma unroll
        for (int f = 0; f < NB; f++)
            wmma::store_matrix_sync(out + (size_t)(row0 + rg * 32 + i * 16) * NCOL +
                                        cg * (NCOL / 2) + f * 16,
                                    acc[i][f], NCOL, wmma::mem_row_major);
}

// ---------------- gather aggregation, d=128: warp/node, 2-wide unroll (measured best) ----------------
__global__ __launch_bounds__(256) void k_agg128(
    const float4* __restrict__ xw, const int* __restrict__ offs,
    const int* __restrict__ bsrc, const float* __restrict__ dinv,
    const float4* __restrict__ bias, float4* __restrict__ h, int n) {
    int t = blockIdx.x * blockDim.x + threadIdx.x;
    int node = t >> 5;
    int lane = t & 31;
    if (node >= n) return;
    float dn = __ldg(dinv + node);
    float4 bb = __ldg(bias + lane);
    float4 acc = f4fma(__ldg(xw + (size_t)node * 32 + lane), dn * dn, bb);
    int beg = __ldg(offs + node), end = __ldg(offs + node + 1);
    int j = beg;
    for (; j + 1 < end; j += 2) {
        int s0 = __ldg(bsrc + j), s1 = __ldg(bsrc + j + 1);
        float n0 = __ldg(dinv + s0) * dn, n1 = __ldg(dinv + s1) * dn;
        float4 v0 = __ldg(xw + (size_t)s0 * 32 + lane);
        float4 v1 = __ldg(xw + (size_t)s1 * 32 + lane);
        acc = f4fma(v0, n0, acc);
        acc = f4fma(v1, n1, acc);
    }
    if (j < end) {
        int s0 = __ldg(bsrc + j);
        acc = f4fma(__ldg(xw + (size_t)s0 * 32 + lane), __ldg(dinv + s0) * dn, acc);
    }
    h[(size_t)node * 32 + lane] = acc;
}

// ---------------- gather aggregation, d=64: warp/node, 2-wide unroll ----------------
__global__ __launch_bounds__(256) void k_agg64(
    const float2* __restrict__ xw, const int* __restrict__ offs,
    const int* __restrict__ bsrc, const float* __restrict__ dinv,
    const float2* __restrict__ bias, float2* __restrict__ h, int n) {
    int t = blockIdx.x * blockDim.x + threadIdx.x;
    int node = t >> 5;
    int lane = t & 31;
    if (node >= n) return;
    float dn = __ldg(dinv + node);
    float2 bb = __ldg(bias + lane);
    float2 v0 = __ldg(xw + (size_t)node * 32 + lane);
    float s = dn * dn;
    float2 acc = make_float2(v0.x * s + bb.x, v0.y * s + bb.y);
    int beg = __ldg(offs + node), end = __ldg(offs + node + 1);
    int j = beg;
    for (; j + 1 < end; j += 2) {
        int s0 = __ldg(bsrc + j), s1 = __ldg(bsrc + j + 1);
        float n0 = __ldg(dinv + s0) * dn, n1 = __ldg(dinv + s1) * dn;
        float2 a = __ldg(xw + (size_t)s0 * 32 + lane);
        float2 b = __ldg(xw + (size_t)s1 * 32 + lane);
        acc.x += a.x * n0 + b.x * n1;
        acc.y += a.y * n0 + b.y * n1;
    }
    if (j < end) {
        int s0 = __ldg(bsrc + j);
        float n0 = __ldg(dinv + s0) * dn;
        float2 a = __ldg(xw + (size_t)s0 * 32 + lane);
        acc.x += a.x * n0; acc.y += a.y * n0;
    }
    h[(size_t)node * 32 + lane] = acc;
}

// ---------------- edge scorer (flat, 16 lanes/edge — measured best) ----------------
__global__ __launch_bounds__(256) void k_score(const float4* __restrict__ h2,
                                               const int* __restrict__ src,
                                               const int* __restrict__ dst,
                                               float* __restrict__ out, int E) {
    int t = blockIdx.x * blockDim.x + threadIdx.x;
    int e = t >> 4;
    int lane = t & 15;
    if (e >= E) return;
    int s = __ldg(src + e);
    int d = __ldg(dst + e);
    float4 a = __ldg(h2 + (size_t)s * 16 + lane);
    float4 b = __ldg(h2 + (size_t)d * 16 + lane);
    float p = a.x * b.x + a.y * b.y + a.z * b.z + a.w * b.w;
#pragma unroll
    for (int off = 8; off; off >>= 1) p += __shfl_xor_sync(0xFFFFFFFFu, p, off);
    if (lane == 0) out[e] = p;
}

static inline int cdiv(long long a, int b) { return (int)((a + b - 1) / b); }

extern "C" void kernel_launch(void* const* d_in, const int* in_sizes, int n_in,
                              void* d_out, int out_size) {
    const float* x   = (const float*)d_in[0];
    const int*   src = (const int*)  d_in[1];
    const int*   dst = (const int*)  d_in[2];
    const float* W1  = (const float*)d_in[3];
    const float* b1  = (const float*)d_in[4];
    const float* W2  = (const float*)d_in[5];
    const float* b2  = (const float*)d_in[6];
    float* score = (float*)d_out;

    int n = in_sizes[0] / DINC;
    int E = in_sizes[1];

    void *p_deg, *p_dinv, *p_offs, *p_cursor, *p_bsrc, *p_xw1, *p_h1, *p_xw2, *p_h2;
    cudaGetSymbolAddress(&p_deg,    g_deg);
    cudaGetSymbolAddress(&p_dinv,   g_dinv);
    cudaGetSymbolAddress(&p_offs,   g_offs);
    cudaGetSymbolAddress(&p_cursor, g_cursor);
    cudaGetSymbolAddress(&p_bsrc,   g_bsrc);
    cudaGetSymbolAddress(&p_xw1,    g_xw1);
    cudaGetSymbolAddress(&p_h1,     g_h1);
    cudaGetSymbolAddress(&p_xw2,    g_xw2);
    cudaGetSymbolAddress(&p_h2,     g_h2);
    int*   deg    = (int*)p_deg;
    float* dinv   = (float*)p_dinv;
    int*   offs   = (int*)p_offs;
    int*   cursor = (int*)p_cursor;
    int*   bsrc   = (int*)p_bsrc;
    float* xw1    = (float*)p_xw1;
    float* h1     = (float*)p_h1;
    float* xw2    = (float*)p_xw2;
    float* h2     = (float*)p_h2;

    const int B = 256;

    // ---- CSR build ----
    cudaMemsetAsync(deg, 0, (size_t)n * sizeof(int));
    k_deg<<<cdiv(E, B), B>>>(dst, deg, E);
    k_scan<<<1, 1024>>>(deg, offs, cursor, dinv, n);
    k_bucket<<<cdiv(E, B), B>>>(src, dst, cursor, bsrc, E);

    // ---- layer 1 (smem-staged tf32 wmma GEMM) ----
    k_gemm_tc<DHC, false><<<cdiv(n, 128), B>>>(x, W1, xw1, n);
    k_agg128<<<cdiv((long long)n * 32, B), B>>>((const float4*)xw1, offs, bsrc, dinv,
                                                (const float4*)b1, (float4*)h1, n);

    // ---- layer 2 (relu fused into GEMM input staging) ----
    k_gemm_tc<DOUTC, true><<<cdiv(n, 128), B>>>(h1, W2, xw2, n);
    k_agg64<<<cdiv((long long)n * 32, B), B>>>((const float2*)xw2, offs, bsrc, dinv,
                                               (const float2*)b2, (float2*)h2, n);

    // ---- edge scores ----
    k_score<<<cdiv((long long)E * 16, B), B>>>((const float4*)h2, src, dst, score, E);
}

// round 10
// speedup vs baseline: 1.6139x; 1.0660x over previous
#include <cuda_runtime.h>
#include <cuda_fp16.h>

#define MAXN 50000
#define MAXE 800000
#define DINC 128
#define DHC  128
#define DOUTC 64

// ---- scratch (static device globals; no allocation allowed) ----
__device__ int    g_deg[MAXN];
__device__ float  g_dinv[MAXN];
__device__ int    g_offs[MAXN + 1];
__device__ int    g_cursor[MAXN];
__device__ int    g_bsrc[MAXE];
__device__ float  g_xw1[MAXN * DHC];
__device__ float  g_h1 [MAXN * DHC];
__device__ float  g_xw2[MAXN * DOUTC];
__device__ __half g_h2h[MAXN * DOUTC];   // fp16: only consumer is the BW-bound scorer

// ---------------- small helpers ----------------
__device__ __forceinline__ float4 f4fma(float4 a, float s, float4 acc) {
    acc.x += a.x * s; acc.y += a.y * s; acc.z += a.z * s; acc.w += a.w * s;
    return acc;
}
__device__ __forceinline__ float4 h4_to_f4(unsigned lo_u, unsigned hi_u) {
    half2 lo = *reinterpret_cast<half2*>(&lo_u);
    half2 hi = *reinterpret_cast<half2*>(&hi_u);
    float2 a = __half22float2(lo), b = __half22float2(hi);
    return make_float4(a.x, a.y, b.x, b.y);
}

// ---------------- degree (1 edge/thread — measured best) ----------------
__global__ void k_deg(const int* __restrict__ dst, int* deg, int E) {
    int e = blockIdx.x * blockDim.x + threadIdx.x;
    if (e < E) atomicAdd(&deg[dst[e]], 1);
}

// ---------------- fused scan: offs (exclusive), cursor copy, dinv ----------------
__global__ void k_scan(const int* __restrict__ deg, int* __restrict__ offs,
                       int* __restrict__ cursor, float* __restrict__ dinv, int n) {
    const int T = 1024;
    __shared__ int s[T];
    int tid = threadIdx.x;
    int per = (n + T - 1) / T;
    int start = tid * per;
    int sum = 0;
    for (int i = 0; i < per; i++) {
        int idx = start + i;
        if (idx < n) sum += deg[idx];
    }
    s[tid] = sum;
    __syncthreads();
    for (int d = 1; d < T; d <<= 1) {
        int v = 0;
        if (tid >= d) v = s[tid - d];
        __syncthreads();
        if (tid >= d) s[tid] += v;
        __syncthreads();
    }
    int run = s[tid] - sum;
    for (int i = 0; i < per; i++) {
        int idx = start + i;
        if (idx < n) {
            int dg = deg[idx];
            offs[idx] = run;
            cursor[idx] = run;
            dinv[idx] = rsqrtf((float)(dg + 1));  // +1 self-loop
            run += dg;
        }
    }
    if (tid == T - 1) offs[n] = run;
}

// ---------------- bucket edges by dst (1 edge/thread — measured best) ----------------
__global__ void k_bucket(const int* __restrict__ src, const int* __restrict__ dst,
                         int* cursor, int* __restrict__ bsrc, int E) {
    int e = blockIdx.x * blockDim.x + threadIdx.x;
    if (e >= E) return;
    int d = dst[e];
    int p = atomicAdd(&cursor[d], 1);
    bsrc[p] = src[e];
}

// ---------------- GEMM: out[n,NCOL] = act(X[n,128]) @ W[128,NCOL] (R2 config) ----------------
template <int NCOL, bool RELU_IN>
__global__ __launch_bounds__(256) void k_gemm(const float* __restrict__ X,
                                              const float* __restrict__ W,
                                              float* __restrict__ out, int n) {
    constexpr int KT = 16;
    constexpr int COLG = NCOL / 4;
    constexpr int RTH = 256 / COLG;
    constexpr int RPT = 64 / RTH;
    __shared__ float Xs[KT][68];
    __shared__ float Ws[KT][NCOL];

    int tid = threadIdx.x;
    int row0 = blockIdx.x * 64;
    int cx = tid % COLG;
    int ry = tid / COLG;

    float4 acc[RPT];
#pragma unroll
    for (int j = 0; j < RPT; j++) acc[j] = make_float4(0.f, 0.f, 0.f, 0.f);

    for (int k0 = 0; k0 < 128; k0 += KT) {
        __syncthreads();
        {
            int rr = tid >> 2;
            int kv = (tid & 3) * 4;
            int row = row0 + rr;
            float4 v = make_float4(0.f, 0.f, 0.f, 0.f);
            if (row < n) v = __ldg(reinterpret_cast<const float4*>(X + row * 128 + k0 + kv));
            if (RELU_IN) {
                v.x = fmaxf(v.x, 0.f); v.y = fmaxf(v.y, 0.f);
                v.z = fmaxf(v.z, 0.f); v.w = fmaxf(v.w, 0.f);
            }
            Xs[kv + 0][rr] = v.x; Xs[kv + 1][rr] = v.y;
            Xs[kv + 2][rr] = v.z; Xs[kv + 3][rr] = v.w;
        }
#pragma unroll
        for (int lin = tid; lin < KT * COLG; lin += 256) {
            int kk = lin / COLG;
            int c = lin % COLG;
            *reinterpret_cast<float4*>(&Ws[kk][c * 4]) =
                __ldg(reinterpret_cast<const float4*>(W + (k0 + kk) * NCOL + c * 4));
        }
        __syncthreads();
#pragma unroll
        for (int kk = 0; kk < KT; kk++) {
            float4 w = *reinterpret_cast<float4*>(&Ws[kk][cx * 4]);
#pragma unroll
            for (int rv = 0; rv < RPT / 4; rv++) {
                float4 xr = *reinterpret_cast<float4*>(&Xs[kk][ry * RPT + rv * 4]);
                acc[rv * 4 + 0] = f4fma(w, xr.x, acc[rv * 4 + 0]);
                acc[rv * 4 + 1] = f4fma(w, xr.y, acc[rv * 4 + 1]);
                acc[rv * 4 + 2] = f4fma(w, xr.z, acc[rv * 4 + 2]);
                acc[rv * 4 + 3] = f4fma(w, xr.w, acc[rv * 4 + 3]);
            }
        }
    }
#pragma unroll
    for (int j = 0; j < RPT; j++) {
        int row = row0 + ry * RPT + j;
        if (row < n)
            *reinterpret_cast<float4*>(out + (size_t)row * NCOL + cx * 4) = acc[j];
    }
}

// ---------------- gather aggregation, d=128: warp/node, 2-wide unroll (R2 config) ----------------
__global__ __launch_bounds__(256) void k_agg128(
    const float4* __restrict__ xw, const int* __restrict__ offs,
    const int* __restrict__ bsrc, const float* __restrict__ dinv,
    const float4* __restrict__ bias, float4* __restrict__ h, int n) {
    int t = blockIdx.x * blockDim.x + threadIdx.x;
    int node = t >> 5;
    int lane = t & 31;
    if (node >= n) return;
    float dn = __ldg(dinv + node);
    float4 bb = __ldg(bias + lane);
    float4 acc = f4fma(__ldg(xw + (size_t)node * 32 + lane), dn * dn, bb);
    int beg = __ldg(offs + node), end = __ldg(offs + node + 1);
    int j = beg;
    for (; j + 1 < end; j += 2) {
        int s0 = __ldg(bsrc + j), s1 = __ldg(bsrc + j + 1);
        float n0 = __ldg(dinv + s0) * dn, n1 = __ldg(dinv + s1) * dn;
        float4 v0 = __ldg(xw + (size_t)s0 * 32 + lane);
        float4 v1 = __ldg(xw + (size_t)s1 * 32 + lane);
        acc = f4fma(v0, n0, acc);
        acc = f4fma(v1, n1, acc);
    }
    if (j < end) {
        int s0 = __ldg(bsrc + j);
        acc = f4fma(__ldg(xw + (size_t)s0 * 32 + lane), __ldg(dinv + s0) * dn, acc);
    }
    h[(size_t)node * 32 + lane] = acc;
}

// ---------------- gather aggregation, d=64: warp/node, 2-wide unroll; fp16 output ----------------
__global__ __launch_bounds__(256) void k_agg64(
    const float2* __restrict__ xw, const int* __restrict__ offs,
    const int* __restrict__ bsrc, const float* __restrict__ dinv,
    const float2* __restrict__ bias, __half* __restrict__ h, int n) {
    int t = blockIdx.x * blockDim.x + threadIdx.x;
    int node = t >> 5;
    int lane = t & 31;
    if (node >= n) return;
    float dn = __ldg(dinv + node);
    float2 bb = __ldg(bias + lane);
    float2 v0 = __ldg(xw + (size_t)node * 32 + lane);
    float s = dn * dn;
    float2 acc = make_float2(v0.x * s + bb.x, v0.y * s + bb.y);
    int beg = __ldg(offs + node), end = __ldg(offs + node + 1);
    int j = beg;
    for (; j + 1 < end; j += 2) {
        int s0 = __ldg(bsrc + j), s1 = __ldg(bsrc + j + 1);
        float n0 = __ldg(dinv + s0) * dn, n1 = __ldg(dinv + s1) * dn;
        float2 a = __ldg(xw + (size_t)s0 * 32 + lane);
        float2 b = __ldg(xw + (size_t)s1 * 32 + lane);
        acc.x += a.x * n0 + b.x * n1;
        acc.y += a.y * n0 + b.y * n1;
    }
    if (j < end) {
        int s0 = __ldg(bsrc + j);
        float n0 = __ldg(dinv + s0) * dn;
        float2 a = __ldg(xw + (size_t)s0 * 32 + lane);
        acc.x += a.x * n0; acc.y += a.y * n0;
    }
    *reinterpret_cast<half2*>(h + (size_t)node * 64 + lane * 2) = __floats2half2_rn(acc.x, acc.y);
}

// ---------------- edge scorer: fp16 h2, 8 lanes/edge, 16B loads (halved L2 traffic) ----------------
__global__ __launch_bounds__(256) void k_score(const __half* __restrict__ h2,
                                               const int* __restrict__ src,
                                               const int* __restrict__ dst,
                                               float* __restrict__ out, int E) {
    int t = blockIdx.x * blockDim.x + threadIdx.x;
    int e = t >> 3;
    int lane = t & 7;
    if (e >= E) return;
    int s = __ldg(src + e);
    int d = __ldg(dst + e);
    uint4 pa = __ldg(reinterpret_cast<const uint4*>(h2 + (size_t)s * 64 + lane * 8));
    uint4 pb = __ldg(reinterpret_cast<const uint4*>(h2 + (size_t)d * 64 + lane * 8));
    float4 a0 = h4_to_f4(pa.x, pa.y);
    float4 a1 = h4_to_f4(pa.z, pa.w);
    float4 b0 = h4_to_f4(pb.x, pb.y);
    float4 b1 = h4_to_f4(pb.z, pb.w);
    float p = a0.x * b0.x + a0.y * b0.y + a0.z * b0.z + a0.w * b0.w
            + a1.x * b1.x + a1.y * b1.y + a1.z * b1.z + a1.w * b1.w;
#pragma unroll
    for (int off = 4; off; off >>= 1) p += __shfl_xor_sync(0xFFFFFFFFu, p, off);
    if (lane == 0) out[e] = p;
}

static inline int cdiv(long long a, int b) { return (int)((a + b - 1) / b); }

extern "C" void kernel_launch(void* const* d_in, const int* in_sizes, int n_in,
                              void* d_out, int out_size) {
    const float* x   = (const float*)d_in[0];
    const int*   src = (const int*)  d_in[1];
    const int*   dst = (const int*)  d_in[2];
    const float* W1  = (const float*)d_in[3];
    const float* b1  = (const float*)d_in[4];
    const float* W2  = (const float*)d_in[5];
    const float* b2  = (const float*)d_in[6];
    float* score = (float*)d_out;

    int n = in_sizes[0] / DINC;
    int E = in_sizes[1];

    void *p_deg, *p_dinv, *p_offs, *p_cursor, *p_bsrc, *p_xw1, *p_h1, *p_xw2, *p_h2;
    cudaGetSymbolAddress(&p_deg,    g_deg);
    cudaGetSymbolAddress(&p_dinv,   g_dinv);
    cudaGetSymbolAddress(&p_offs,   g_offs);
    cudaGetSymbolAddress(&p_cursor, g_cursor);
    cudaGetSymbolAddress(&p_bsrc,   g_bsrc);
    cudaGetSymbolAddress(&p_xw1,    g_xw1);
    cudaGetSymbolAddress(&p_h1,     g_h1);
    cudaGetSymbolAddress(&p_xw2,    g_xw2);
    cudaGetSymbolAddress(&p_h2,     g_h2h);
    int*    deg    = (int*)p_deg;
    float*  dinv   = (float*)p_dinv;
    int*    offs   = (int*)p_offs;
    int*    cursor = (int*)p_cursor;
    int*    bsrc   = (int*)p_bsrc;
    float*  xw1    = (float*)p_xw1;
    float*  h1     = (float*)p_h1;
    float*  xw2    = (float*)p_xw2;
    __half* h2     = (__half*)p_h2;

    const int B = 256;

    // ---- CSR build ----
    cudaMemsetAsync(deg, 0, (size_t)n * sizeof(int));
    k_deg<<<cdiv(E, B), B>>>(dst, deg, E);
    k_scan<<<1, 1024>>>(deg, offs, cursor, dinv, n);
    k_bucket<<<cdiv(E, B), B>>>(src, dst, cursor, bsrc, E);

    // ---- layer 1 (R2 config, all fp32) ----
    k_gemm<DHC, false><<<cdiv(n, 64), B>>>(x, W1, xw1, n);
    k_agg128<<<cdiv((long long)n * 32, B), B>>>((const float4*)xw1, offs, bsrc, dinv,
                                                (const float4*)b1, (float4*)h1, n);

    // ---- layer 2 (relu fused into GEMM input; fp16 only at h2 output) ----
    k_gemm<DOUTC, true><<<cdiv(n, 64), B>>>(h1, W2, xw2, n);
    k_agg64<<<cdiv((long long)n * 32, B), B>>>((const float2*)xw2, offs, bsrc, dinv,
                                               (const float2*)b2, h2, n);

    // ---- edge scores ----
    k_score<<<cdiv((long long)E * 8, B), B>>>(h2, src, dst, score, E);
}

// round 11
// speedup vs baseline: 1.8875x; 1.1696x over previous
#include <cuda_runtime.h>

#define MAXN 50000
#define MAXE 800000
#define DINC 128
#define DHC  128
#define DOUTC 64

// ---- scratch (static device globals; no allocation allowed) ----
__device__ int   g_deg[MAXN];
__device__ float g_dinv[MAXN];
__device__ int   g_offs[MAXN + 1];
__device__ int   g_cursor[MAXN];
__device__ int   g_bsrc[MAXE];
__device__ float g_xw1[MAXN * DHC];
__device__ float g_h1 [MAXN * DHC];
__device__ float g_xw2[MAXN * DOUTC];
__device__ float g_h2 [MAXN * DOUTC];

// ---------------- small helpers ----------------
__device__ __forceinline__ float4 f4fma(float4 a, float s, float4 acc) {
    acc.x += a.x * s; acc.y += a.y * s; acc.z += a.z * s; acc.w += a.w * s;
    return acc;
}

// ---------------- degree / norm (R2 exact) ----------------
__global__ void k_deg(const int* __restrict__ dst, int* deg, int E) {
    int e = blockIdx.x * blockDim.x + threadIdx.x;
    if (e < E) atomicAdd(&deg[dst[e]], 1);
}
__global__ void k_dinv(const int* __restrict__ deg, float* dinv, int n) {
    int i = blockIdx.x * blockDim.x + threadIdx.x;
    if (i < n) dinv[i] = rsqrtf((float)(deg[i] + 1));  // +1 self-loop
}

// ---------------- single-block exclusive scan over deg -> offs[0..n] (R2 exact) ----------------
__global__ void k_scan(const int* __restrict__ deg, int* __restrict__ offs, int n) {
    const int T = 1024;
    __shared__ int s[T];
    int tid = threadIdx.x;
    int per = (n + T - 1) / T;
    int start = tid * per;
    int sum = 0;
    for (int i = 0; i < per; i++) {
        int idx = start + i;
        if (idx < n) sum += deg[idx];
    }
    s[tid] = sum;
    __syncthreads();
    for (int d = 1; d < T; d <<= 1) {
        int v = 0;
        if (tid >= d) v = s[tid - d];
        __syncthreads();
        if (tid >= d) s[tid] += v;
        __syncthreads();
    }
    int run = s[tid] - sum;  // exclusive prefix of this chunk
    for (int i = 0; i < per; i++) {
        int idx = start + i;
        if (idx < n) {
            offs[idx] = run;
            run += deg[idx];
        }
    }
    if (tid == T - 1) offs[n] = run;  // total = E
}

// ---------------- bucket edges by dst (R2 exact) ----------------
__global__ void k_bucket(const int* __restrict__ src, const int* __restrict__ dst,
                         int* cursor, int* __restrict__ bsrc, int E) {
    int e = blockIdx.x * blockDim.x + threadIdx.x;
    if (e >= E) return;
    int d = dst[e];
    int p = atomicAdd(&cursor[d], 1);
    bsrc[p] = src[e];
}

// ---------------- GEMM: out[n,NCOL] = act(X[n,128]) @ W[128,NCOL] (R2 exact) ----------------
template <int NCOL, bool RELU_IN>
__global__ __launch_bounds__(256) void k_gemm(const float* __restrict__ X,
                                              const float* __restrict__ W,
                                              float* __restrict__ out, int n) {
    constexpr int KT = 16;
    constexpr int COLG = NCOL / 4;
    constexpr int RTH = 256 / COLG;
    constexpr int RPT = 64 / RTH;
    __shared__ float Xs[KT][68];
    __shared__ float Ws[KT][NCOL];

    int tid = threadIdx.x;
    int row0 = blockIdx.x * 64;
    int cx = tid % COLG;
    int ry = tid / COLG;

    float4 acc[RPT];
#pragma unroll
    for (int j = 0; j < RPT; j++) acc[j] = make_float4(0.f, 0.f, 0.f, 0.f);

    for (int k0 = 0; k0 < 128; k0 += KT) {
        __syncthreads();
        {
            int rr = tid >> 2;
            int kv = (tid & 3) * 4;
            int row = row0 + rr;
            float4 v = make_float4(0.f, 0.f, 0.f, 0.f);
            if (row < n) v = __ldg(reinterpret_cast<const float4*>(X + row * 128 + k0 + kv));
            if (RELU_IN) {
                v.x = fmaxf(v.x, 0.f); v.y = fmaxf(v.y, 0.f);
                v.z = fmaxf(v.z, 0.f); v.w = fmaxf(v.w, 0.f);
            }
            Xs[kv + 0][rr] = v.x; Xs[kv + 1][rr] = v.y;
            Xs[kv + 2][rr] = v.z; Xs[kv + 3][rr] = v.w;
        }
#pragma unroll
        for (int lin = tid; lin < KT * COLG; lin += 256) {
            int kk = lin / COLG;
            int c = lin % COLG;
            *reinterpret_cast<float4*>(&Ws[kk][c * 4]) =
                __ldg(reinterpret_cast<const float4*>(W + (k0 + kk) * NCOL + c * 4));
        }
        __syncthreads();
#pragma unroll
        for (int kk = 0; kk < KT; kk++) {
            float4 w = *reinterpret_cast<float4*>(&Ws[kk][cx * 4]);
#pragma unroll
            for (int rv = 0; rv < RPT / 4; rv++) {
                float4 xr = *reinterpret_cast<float4*>(&Xs[kk][ry * RPT + rv * 4]);
                acc[rv * 4 + 0] = f4fma(w, xr.x, acc[rv * 4 + 0]);
                acc[rv * 4 + 1] = f4fma(w, xr.y, acc[rv * 4 + 1]);
                acc[rv * 4 + 2] = f4fma(w, xr.z, acc[rv * 4 + 2]);
                acc[rv * 4 + 3] = f4fma(w, xr.w, acc[rv * 4 + 3]);
            }
        }
    }
#pragma unroll
    for (int j = 0; j < RPT; j++) {
        int row = row0 + ry * RPT + j;
        if (row < n)
            *reinterpret_cast<float4*>(out + row * NCOL + cx * 4) = acc[j];
    }
}

// ---------------- gather aggregation, d=128 (R2 exact) ----------------
__global__ __launch_bounds__(256) void k_agg128(
    const float4* __restrict__ xw, const int* __restrict__ offs,
    const int* __restrict__ bsrc, const float* __restrict__ dinv,
    const float4* __restrict__ bias, float4* __restrict__ h, int n) {
    int t = blockIdx.x * blockDim.x + threadIdx.x;
    int node = t >> 5;
    int lane = t & 31;
    if (node >= n) return;
    float dn = __ldg(dinv + node);
    float4 bb = __ldg(bias + lane);
    float4 acc = f4fma(__ldg(xw + (size_t)node * 32 + lane), dn * dn, bb);
    int beg = __ldg(offs + node), end = __ldg(offs + node + 1);
    int j = beg;
    for (; j + 1 < end; j += 2) {
        int s0 = __ldg(bsrc + j), s1 = __ldg(bsrc + j + 1);
        float n0 = __ldg(dinv + s0) * dn, n1 = __ldg(dinv + s1) * dn;
        float4 v0 = __ldg(xw + (size_t)s0 * 32 + lane);
        float4 v1 = __ldg(xw + (size_t)s1 * 32 + lane);
        acc = f4fma(v0, n0, acc);
        acc = f4fma(v1, n1, acc);
    }
    if (j < end) {
        int s0 = __ldg(bsrc + j);
        acc = f4fma(__ldg(xw + (size_t)s0 * 32 + lane), __ldg(dinv + s0) * dn, acc);
    }
    h[(size_t)node * 32 + lane] = acc;
}

// ---------------- gather aggregation, d=64 (R2 exact) ----------------
__global__ __launch_bounds__(256) void k_agg64(
    const float2* __restrict__ xw, const int* __restrict__ offs,
    const int* __restrict__ bsrc, const float* __restrict__ dinv,
    const float2* __restrict__ bias, float2* __restrict__ h, int n) {
    int t = blockIdx.x * blockDim.x + threadIdx.x;
    int node = t >> 5;
    int lane = t & 31;
    if (node >= n) return;
    float dn = __ldg(dinv + node);
    float2 bb = __ldg(bias + lane);
    float2 v0 = __ldg(xw + (size_t)node * 32 + lane);
    float s = dn * dn;
    float2 acc = make_float2(v0.x * s + bb.x, v0.y * s + bb.y);
    int beg = __ldg(offs + node), end = __ldg(offs + node + 1);
    int j = beg;
    for (; j + 1 < end; j += 2) {
        int s0 = __ldg(bsrc + j), s1 = __ldg(bsrc + j + 1);
        float n0 = __ldg(dinv + s0) * dn, n1 = __ldg(dinv + s1) * dn;
        float2 a = __ldg(xw + (size_t)s0 * 32 + lane);
        float2 b = __ldg(xw + (size_t)s1 * 32 + lane);
        acc.x += a.x * n0 + b.x * n1;
        acc.y += a.y * n0 + b.y * n1;
    }
    if (j < end) {
        int s0 = __ldg(bsrc + j);
        float n0 = __ldg(dinv + s0) * dn;
        float2 a = __ldg(xw + (size_t)s0 * 32 + lane);
        acc.x += a.x * n0; acc.y += a.y * n0;
    }
    h[(size_t)node * 32 + lane] = acc;
}

// ---------------- edge scorer (R2 exact: fp32, 16 lanes/edge) ----------------
__global__ __launch_bounds__(256) void k_score(const float4* __restrict__ h2,
                                               const int* __restrict__ src,
                                               const int* __restrict__ dst,
                                               float* __restrict__ out, int E) {
    int t = blockIdx.x * blockDim.x + threadIdx.x;
    int e = t >> 4;
    int lane = t & 15;
    if (e >= E) return;
    int s = __ldg(src + e);
    int d = __ldg(dst + e);
    float4 a = __ldg(h2 + (size_t)s * 16 + lane);
    float4 b = __ldg(h2 + (size_t)d * 16 + lane);
    float p = a.x * b.x + a.y * b.y + a.z * b.z + a.w * b.w;
#pragma unroll
    for (int off = 8; off; off >>= 1) p += __shfl_xor_sync(0xFFFFFFFFu, p, off);
    if (lane == 0) out[e] = p;
}

static inline int cdiv(long long a, int b) { return (int)((a + b - 1) / b); }

extern "C" void kernel_launch(void* const* d_in, const int* in_sizes, int n_in,
                              void* d_out, int out_size) {
    const float* x   = (const float*)d_in[0];
    const int*   src = (const int*)  d_in[1];
    const int*   dst = (const int*)  d_in[2];
    const float* W1  = (const float*)d_in[3];
    const float* b1  = (const float*)d_in[4];
    const float* W2  = (const float*)d_in[5];
    const float* b2  = (const float*)d_in[6];
    float* score = (float*)d_out;

    int n = in_sizes[0] / DINC;
    int E = in_sizes[1];

    void *p_deg, *p_dinv, *p_offs, *p_cursor, *p_bsrc, *p_xw1, *p_h1, *p_xw2, *p_h2;
    cudaGetSymbolAddress(&p_deg,    g_deg);
    cudaGetSymbolAddress(&p_dinv,   g_dinv);
    cudaGetSymbolAddress(&p_offs,   g_offs);
    cudaGetSymbolAddress(&p_cursor, g_cursor);
    cudaGetSymbolAddress(&p_bsrc,   g_bsrc);
    cudaGetSymbolAddress(&p_xw1,    g_xw1);
    cudaGetSymbolAddress(&p_h1,     g_h1);
    cudaGetSymbolAddress(&p_xw2,    g_xw2);
    cudaGetSymbolAddress(&p_h2,     g_h2);
    int*   deg    = (int*)p_deg;
    float* dinv   = (float*)p_dinv;
    int*   offs   = (int*)p_offs;
    int*   cursor = (int*)p_cursor;
    int*   bsrc   = (int*)p_bsrc;
    float* xw1    = (float*)p_xw1;
    float* h1     = (float*)p_h1;
    float* xw2    = (float*)p_xw2;
    float* h2     = (float*)p_h2;

    // one-time host resources (no device allocation; streams/events only)
    static cudaStream_t s2 = nullptr;
    static cudaEvent_t evFork = nullptr, evJoin = nullptr;
    if (!s2) {
        cudaStreamCreateWithFlags(&s2, cudaStreamNonBlocking);
        cudaEventCreateWithFlags(&evFork, cudaEventDisableTiming);
        cudaEventCreateWithFlags(&evJoin, cudaEventDisableTiming);
    }

    const int B = 256;

    // ---- fork: GEMM1 (features only) on s2, CSR build (graph only) on capture stream ----
    cudaEventRecord(evFork, 0);
    cudaStreamWaitEvent(s2, evFork, 0);
    k_gemm<DHC, false><<<cdiv(n, 64), B, 0, s2>>>(x, W1, xw1, n);
    cudaEventRecord(evJoin, s2);

    // CSR build — R2-exact kernels (1-edge/thread atomics, separate dinv, memcpy cursor)
    cudaMemsetAsync(deg, 0, (size_t)n * sizeof(int));
    k_deg<<<cdiv(E, B), B>>>(dst, deg, E);
    k_dinv<<<cdiv(n, B), B>>>(deg, dinv, n);
    k_scan<<<1, 1024>>>(deg, offs, n);
    cudaMemcpyAsync(cursor, offs, (size_t)n * sizeof(int), cudaMemcpyDeviceToDevice);
    k_bucket<<<cdiv(E, B), B>>>(src, dst, cursor, bsrc, E);

    // ---- join: agg128 needs bucket (this stream) + gemm1 (s2) ----
    cudaStreamWaitEvent(0, evJoin, 0);
    k_agg128<<<cdiv((long long)n * 32, B), B>>>((const float4*)xw1, offs, bsrc, dinv,
                                                (const float4*)b1, (float4*)h1, n);

    // ---- layer 2 (relu fused into GEMM input) ----
    k_gemm<DOUTC, true><<<cdiv(n, 64), B>>>(h1, W2, xw2, n);
    k_agg64<<<cdiv((long long)n * 32, B), B>>>((const float2*)xw2, offs, bsrc, dinv,
                                               (const float2*)b2, (float2*)h2, n);

    // ---- edge scores ----
    k_score<<<cdiv((long long)E * 16, B), B>>>((const float4*)h2, src, dst, score, E);
}

// round 13
// speedup vs baseline: 2.2950x; 1.2159x over previous
#include <cuda_runtime.h>

#define MAXN 50000
#define MAXE 800000
#define DINC 128
#define DHC  128
#define DOUTC 64
#define SCHUNK 256
#define MAXNB ((MAXN + SCHUNK - 1) / SCHUNK)

// ---- scratch (static device globals; no allocation allowed) ----
__device__ int   g_deg[MAXN];
__device__ float g_dinv[MAXN];
__device__ int   g_offs[MAXN + 1];
__device__ int   g_cursor[MAXN];
__device__ int   g_bsrc[MAXE];
__device__ int   g_bsum[MAXNB];
__device__ int   g_bpre[MAXNB];
__device__ float g_xw1[MAXN * DHC];
__device__ float g_h1 [MAXN * DHC];
__device__ float g_xw2[MAXN * DOUTC];
__device__ float g_h2 [MAXN * DOUTC];

// ---------------- small helpers ----------------
__device__ __forceinline__ float4 f4fma(float4 a, float s, float4 acc) {
    acc.x += a.x * s; acc.y += a.y * s; acc.z += a.z * s; acc.w += a.w * s;
    return acc;
}

// ---------------- degree (1 edge/thread — measured best) ----------------
__global__ void k_deg(const int* __restrict__ dst, int* deg, int E) {
    int e = blockIdx.x * blockDim.x + threadIdx.x;
    if (e < E) atomicAdd(&deg[dst[e]], 1);
}

// ---------------- two-level scan: A) per-block sums ----------------
__global__ void k_scan_a(const int* __restrict__ deg, int* __restrict__ bsum, int n) {
    __shared__ int s[SCHUNK];
    int idx = blockIdx.x * SCHUNK + threadIdx.x;
    s[threadIdx.x] = (idx < n) ? deg[idx] : 0;
    __syncthreads();
    for (int d = SCHUNK / 2; d > 0; d >>= 1) {
        if (threadIdx.x < d) s[threadIdx.x] += s[threadIdx.x + d];
        __syncthreads();
    }
    if (threadIdx.x == 0) bsum[blockIdx.x] = s[0];
}

// ---------------- B) single small block scans block sums; writes offs[n] ----------------
__global__ void k_scan_b(const int* __restrict__ bsum, int* __restrict__ bpre,
                         int* __restrict__ offs, int nb, int n) {
    const int T = 1024;
    __shared__ int s[T];
    int tid = threadIdx.x;
    int v = (tid < nb) ? bsum[tid] : 0;
    s[tid] = v;
    __syncthreads();
    for (int d = 1; d < T; d <<= 1) {
        int t = 0;
        if (tid >= d) t = s[tid - d];
        __syncthreads();
        if (tid >= d) s[tid] += t;
        __syncthreads();
    }
    if (tid < nb) bpre[tid] = s[tid] - v;   // exclusive prefix
    if (tid == T - 1) offs[n] = s[T - 1];   // total = E
}

// ---------------- C) per-chunk exclusive scan; writes offs, cursor, dinv ----------------
__global__ void k_scan_c(const int* __restrict__ deg, const int* __restrict__ bpre,
                         int* __restrict__ offs, int* __restrict__ cursor,
                         float* __restrict__ dinv, int n) {
    __shared__ int s[SCHUNK];
    int idx = blockIdx.x * SCHUNK + threadIdx.x;
    int dg = (idx < n) ? deg[idx] : 0;
    s[threadIdx.x] = dg;
    __syncthreads();
    // Hillis-Steele inclusive scan over the chunk
    for (int d = 1; d < SCHUNK; d <<= 1) {
        int t = 0;
        if (threadIdx.x >= d) t = s[threadIdx.x - d];
        __syncthreads();
        if (threadIdx.x >= d) s[threadIdx.x] += t;
        __syncthreads();
    }
    if (idx < n) {
        int off = bpre[blockIdx.x] + s[threadIdx.x] - dg;  // exclusive
        offs[idx] = off;
        cursor[idx] = off;
        dinv[idx] = rsqrtf((float)(dg + 1));  // +1 self-loop
    }
}

// ---------------- bucket edges by dst (1 edge/thread — measured best) ----------------
__global__ void k_bucket(const int* __restrict__ src, const int* __restrict__ dst,
                         int* cursor, int* __restrict__ bsrc, int E) {
    int e = blockIdx.x * blockDim.x + threadIdx.x;
    if (e >= E) return;
    int d = dst[e];
    int p = atomicAdd(&cursor[d], 1);
    bsrc[p] = src[e];
}

// ---------------- GEMM: out[n,NCOL] = act(X[n,128]) @ W[128,NCOL] (R2 exact) ----------------
template <int NCOL, bool RELU_IN>
__global__ __launch_bounds__(256) void k_gemm(const float* __restrict__ X,
                                              const float* __restrict__ W,
                                              float* __restrict__ out, int n) {
    constexpr int KT = 16;
    constexpr int COLG = NCOL / 4;
    constexpr int RTH = 256 / COLG;
    constexpr int RPT = 64 / RTH;
    __shared__ float Xs[KT][68];
    __shared__ float Ws[KT][NCOL];

    int tid = threadIdx.x;
    int row0 = blockIdx.x * 64;
    int cx = tid % COLG;
    int ry = tid / COLG;

    float4 acc[RPT];
#pragma unroll
    for (int j = 0; j < RPT; j++) acc[j] = make_float4(0.f, 0.f, 0.f, 0.f);

    for (int k0 = 0; k0 < 128; k0 += KT) {
        __syncthreads();
        {
            int rr = tid >> 2;
            int kv = (tid & 3) * 4;
            int row = row0 + rr;
            float4 v = make_float4(0.f, 0.f, 0.f, 0.f);
            if (row < n) v = __ldg(reinterpret_cast<const float4*>(X + row * 128 + k0 + kv));
            if (RELU_IN) {
                v.x = fmaxf(v.x, 0.f); v.y = fmaxf(v.y, 0.f);
                v.z = fmaxf(v.z, 0.f); v.w = fmaxf(v.w, 0.f);
            }
            Xs[kv + 0][rr] = v.x; Xs[kv + 1][rr] = v.y;
            Xs[kv + 2][rr] = v.z; Xs[kv + 3][rr] = v.w;
        }
#pragma unroll
        for (int lin = tid; lin < KT * COLG; lin += 256) {
            int kk = lin / COLG;
            int c = lin % COLG;
            *reinterpret_cast<float4*>(&Ws[kk][c * 4]) =
                __ldg(reinterpret_cast<const float4*>(W + (k0 + kk) * NCOL + c * 4));
        }
        __syncthreads();
#pragma unroll
        for (int kk = 0; kk < KT; kk++) {
            float4 w = *reinterpret_cast<float4*>(&Ws[kk][cx * 4]);
#pragma unroll
            for (int rv = 0; rv < RPT / 4; rv++) {
                float4 xr = *reinterpret_cast<float4*>(&Xs[kk][ry * RPT + rv * 4]);
                acc[rv * 4 + 0] = f4fma(w, xr.x, acc[rv * 4 + 0]);
                acc[rv * 4 + 1] = f4fma(w, xr.y, acc[rv * 4 + 1]);
                acc[rv * 4 + 2] = f4fma(w, xr.z, acc[rv * 4 + 2]);
                acc[rv * 4 + 3] = f4fma(w, xr.w, acc[rv * 4 + 3]);
            }
        }
    }
#pragma unroll
    for (int j = 0; j < RPT; j++) {
        int row = row0 + ry * RPT + j;
        if (row < n)
            *reinterpret_cast<float4*>(out + row * NCOL + cx * 4) = acc[j];
    }
}

// ---------------- gather aggregation, d=128 (R2 exact) ----------------
__global__ __launch_bounds__(256) void k_agg128(
    const float4* __restrict__ xw, const int* __restrict__ offs,
    const int* __restrict__ bsrc, const float* __restrict__ dinv,
    const float4* __restrict__ bias, float4* __restrict__ h, int n) {
    int t = blockIdx.x * blockDim.x + threadIdx.x;
    int node = t >> 5;
    int lane = t & 31;
    if (node >= n) return;
    float dn = __ldg(dinv + node);
    float4 bb = __ldg(bias + lane);
    float4 acc = f4fma(__ldg(xw + (size_t)node * 32 + lane), dn * dn, bb);
    int beg = __ldg(offs + node), end = __ldg(offs + node + 1);
    int j = beg;
    for (; j + 1 < end; j += 2) {
        int s0 = __ldg(bsrc + j), s1 = __ldg(bsrc + j + 1);
        float n0 = __ldg(dinv + s0) * dn, n1 = __ldg(dinv + s1) * dn;
        float4 v0 = __ldg(xw + (size_t)s0 * 32 + lane);
        float4 v1 = __ldg(xw + (size_t)s1 * 32 + lane);
        acc = f4fma(v0, n0, acc);
        acc = f4fma(v1, n1, acc);
    }
    if (j < end) {
        int s0 = __ldg(bsrc + j);
        acc = f4fma(__ldg(xw + (size_t)s0 * 32 + lane), __ldg(dinv + s0) * dn, acc);
    }
    h[(size_t)node * 32 + lane] = acc;
}

// ---------------- gather aggregation, d=64 (R2 exact) ----------------
__global__ __launch_bounds__(256) void k_agg64(
    const float2* __restrict__ xw, const int* __restrict__ offs,
    const int* __restrict__ bsrc, const float* __restrict__ dinv,
    const float2* __restrict__ bias, float2* __restrict__ h, int n) {
    int t = blockIdx.x * blockDim.x + threadIdx.x;
    int node = t >> 5;
    int lane = t & 31;
    if (node >= n) return;
    float dn = __ldg(dinv + node);
    float2 bb = __ldg(bias + lane);
    float2 v0 = __ldg(xw + (size_t)node * 32 + lane);
    float s = dn * dn;
    float2 acc = make_float2(v0.x * s + bb.x, v0.y * s + bb.y);
    int beg = __ldg(offs + node), end = __ldg(offs + node + 1);
    int j = beg;
    for (; j + 1 < end; j += 2) {
        int s0 = __ldg(bsrc + j), s1 = __ldg(bsrc + j + 1);
        float n0 = __ldg(dinv + s0) * dn, n1 = __ldg(dinv + s1) * dn;
        float2 a = __ldg(xw + (size_t)s0 * 32 + lane);
        float2 b = __ldg(xw + (size_t)s1 * 32 + lane);
        acc.x += a.x * n0 + b.x * n1;
        acc.y += a.y * n0 + b.y * n1;
    }
    if (j < end) {
        int s0 = __ldg(bsrc + j);
        float n0 = __ldg(dinv + s0) * dn;
        float2 a = __ldg(xw + (size_t)s0 * 32 + lane);
        acc.x += a.x * n0; acc.y += a.y * n0;
    }
    h[(size_t)node * 32 + lane] = acc;
}

// ---------------- edge scorer (R2 exact: fp32, 16 lanes/edge) ----------------
__global__ __launch_bounds__(256) void k_score(const float4* __restrict__ h2,
                                               const int* __restrict__ src,
                                               const int* __restrict__ dst,
                                               float* __restrict__ out, int E) {
    int t = blockIdx.x * blockDim.x + threadIdx.x;
    int e = t >> 4;
    int lane = t & 15;
    if (e >= E) return;
    int s = __ldg(src + e);
    int d = __ldg(dst + e);
    float4 a = __ldg(h2 + (size_t)s * 16 + lane);
    float4 b = __ldg(h2 + (size_t)d * 16 + lane);
    float p = a.x * b.x + a.y * b.y + a.z * b.z + a.w * b.w;
#pragma unroll
    for (int off = 8; off; off >>= 1) p += __shfl_xor_sync(0xFFFFFFFFu, p, off);
    if (lane == 0) out[e] = p;
}

static inline int cdiv(long long a, int b) { return (int)((a + b - 1) / b); }

extern "C" void kernel_launch(void* const* d_in, const int* in_sizes, int n_in,
                              void* d_out, int out_size) {
    const float* x   = (const float*)d_in[0];
    const int*   src = (const int*)  d_in[1];
    const int*   dst = (const int*)  d_in[2];
    const float* W1  = (const float*)d_in[3];
    const float* b1  = (const float*)d_in[4];
    const float* W2  = (const float*)d_in[5];
    const float* b2  = (const float*)d_in[6];
    float* score = (float*)d_out;

    int n = in_sizes[0] / DINC;
    int E = in_sizes[1];
    int nb = cdiv(n, SCHUNK);

    void *p_deg, *p_dinv, *p_offs, *p_cursor, *p_bsrc, *p_bsum, *p_bpre,
         *p_xw1, *p_h1, *p_xw2, *p_h2;
    cudaGetSymbolAddress(&p_deg,    g_deg);
    cudaGetSymbolAddress(&p_dinv,   g_dinv);
    cudaGetSymbolAddress(&p_offs,   g_offs);
    cudaGetSymbolAddress(&p_cursor, g_cursor);
    cudaGetSymbolAddress(&p_bsrc,   g_bsrc);
    cudaGetSymbolAddress(&p_bsum,   g_bsum);
    cudaGetSymbolAddress(&p_bpre,   g_bpre);
    cudaGetSymbolAddress(&p_xw1,    g_xw1);
    cudaGetSymbolAddress(&p_h1,     g_h1);
    cudaGetSymbolAddress(&p_xw2,    g_xw2);
    cudaGetSymbolAddress(&p_h2,     g_h2);
    int*   deg    = (int*)p_deg;
    float* dinv   = (float*)p_dinv;
    int*   offs   = (int*)p_offs;
    int*   cursor = (int*)p_cursor;
    int*   bsrc   = (int*)p_bsrc;
    int*   bsum   = (int*)p_bsum;
    int*   bpre   = (int*)p_bpre;
    float* xw1    = (float*)p_xw1;
    float* h1     = (float*)p_h1;
    float* xw2    = (float*)p_xw2;
    float* h2     = (float*)p_h2;

    // one-time host resources (no device allocation; streams/events only)
    static cudaStream_t s2 = nullptr;
    static cudaEvent_t evFork = nullptr, evJoin = nullptr;
    if (!s2) {
        cudaStreamCreateWithFlags(&s2, cudaStreamNonBlocking);
        cudaEventCreateWithFlags(&evFork, cudaEventDisableTiming);
        cudaEventCreateWithFlags(&evJoin, cudaEventDisableTiming);
    }

    const int B = 256;

    // ---- fork: GEMM1 (features only) on s2, CSR build (graph only) on capture stream ----
    cudaEventRecord(evFork, 0);
    cudaStreamWaitEvent(s2, evFork, 0);
    k_gemm<DHC, false><<<cdiv(n, 64), B, 0, s2>>>(x, W1, xw1, n);
    cudaEventRecord(evJoin, s2);

    // CSR build — parallel two-level scan (replaces 46us single-block scan)
    cudaMemsetAsync(deg, 0, (size_t)n * sizeof(int));
    k_deg<<<cdiv(E, B), B>>>(dst, deg, E);
    k_scan_a<<<nb, SCHUNK>>>(deg, bsum, n);
    k_scan_b<<<1, 1024>>>(bsum, bpre, offs, nb, n);
    k_scan_c<<<nb, SCHUNK>>>(deg, bpre, offs, cursor, dinv, n);
    k_bucket<<<cdiv(E, B), B>>>(src, dst, cursor, bsrc, E);

    // ---- join: agg128 needs bucket (this stream) + gemm1 (s2) ----
    cudaStreamWaitEvent(0, evJoin, 0);
    k_agg128<<<cdiv((long long)n * 32, B), B>>>((const float4*)xw1, offs, bsrc, dinv,
                                                (const float4*)b1, (float4*)h1, n);

    // ---- layer 2 (relu fused into GEMM input) ----
    k_gemm<DOUTC, true><<<cdiv(n, 64), B>>>(h1, W2, xw2, n);
    k_agg64<<<cdiv((long long)n * 32, B), B>>>((const float2*)xw2, offs, bsrc, dinv,
                                               (const float2*)b2, (float2*)h2, n);

    // ---- edge scores ----
    k_score<<<cdiv((long long)E * 16, B), B>>>((const float4*)h2, src, dst, score, E);
}

// round 14
// speedup vs baseline: 2.6073x; 1.1360x over previous
#include <cuda_runtime.h>
#include <cuda_fp16.h>

#define MAXN 50000
#define MAXE 800000
#define DINC 128
#define DHC  128
#define DOUTC 64
#define SCHUNK 256
#define MAXNB ((MAXN + SCHUNK - 1) / SCHUNK)

// ---- scratch (static device globals; no allocation allowed) ----
__device__ int    g_deg[MAXN];
__device__ float  g_dinv[MAXN];
__device__ int    g_offs[MAXN + 1];
__device__ int    g_cursor[MAXN];
__device__ int    g_bsrc[MAXE];
__device__ int    g_bsum[MAXNB];
__device__ int    g_bpre[MAXNB];
__device__ float  g_xw1[MAXN * DHC];
__device__ float  g_h1 [MAXN * DHC];
__device__ float  g_xw2[MAXN * DOUTC];
__device__ __half g_h2h[MAXN * DOUTC];   // fp16: halves the scorer's 410MB L2 gather

// ---------------- small helpers ----------------
__device__ __forceinline__ float4 f4fma(float4 a, float s, float4 acc) {
    acc.x += a.x * s; acc.y += a.y * s; acc.z += a.z * s; acc.w += a.w * s;
    return acc;
}
__device__ __forceinline__ float4 h4_to_f4(unsigned lo_u, unsigned hi_u) {
    half2 lo = *reinterpret_cast<half2*>(&lo_u);
    half2 hi = *reinterpret_cast<half2*>(&hi_u);
    float2 a = __half22float2(lo), b = __half22float2(hi);
    return make_float4(a.x, a.y, b.x, b.y);
}

// ---------------- degree (1 edge/thread — measured best) ----------------
__global__ void k_deg(const int* __restrict__ dst, int* deg, int E) {
    int e = blockIdx.x * blockDim.x + threadIdx.x;
    if (e < E) atomicAdd(&deg[dst[e]], 1);
}

// ---------------- two-level scan: A) per-block sums ----------------
__global__ void k_scan_a(const int* __restrict__ deg, int* __restrict__ bsum, int n) {
    __shared__ int s[SCHUNK];
    int idx = blockIdx.x * SCHUNK + threadIdx.x;
    s[threadIdx.x] = (idx < n) ? deg[idx] : 0;
    __syncthreads();
    for (int d = SCHUNK / 2; d > 0; d >>= 1) {
        if (threadIdx.x < d) s[threadIdx.x] += s[threadIdx.x + d];
        __syncthreads();
    }
    if (threadIdx.x == 0) bsum[blockIdx.x] = s[0];
}

// ---------------- B) single small block scans block sums; writes offs[n] ----------------
__global__ void k_scan_b(const int* __restrict__ bsum, int* __restrict__ bpre,
                         int* __restrict__ offs, int nb, int n) {
    const int T = 1024;
    __shared__ int s[T];
    int tid = threadIdx.x;
    int v = (tid < nb) ? bsum[tid] : 0;
    s[tid] = v;
    __syncthreads();
    for (int d = 1; d < T; d <<= 1) {
        int t = 0;
        if (tid >= d) t = s[tid - d];
        __syncthreads();
        if (tid >= d) s[tid] += t;
        __syncthreads();
    }
    if (tid < nb) bpre[tid] = s[tid] - v;   // exclusive prefix
    if (tid == T - 1) offs[n] = s[T - 1];   // total = E
}

// ---------------- C) per-chunk exclusive scan; writes offs, cursor, dinv ----------------
__global__ void k_scan_c(const int* __restrict__ deg, const int* __restrict__ bpre,
                         int* __restrict__ offs, int* __restrict__ cursor,
                         float* __restrict__ dinv, int n) {
    __shared__ int s[SCHUNK];
    int idx = blockIdx.x * SCHUNK + threadIdx.x;
    int dg = (idx < n) ? deg[idx] : 0;
    s[threadIdx.x] = dg;
    __syncthreads();
    for (int d = 1; d < SCHUNK; d <<= 1) {
        int t = 0;
        if (threadIdx.x >= d) t = s[threadIdx.x - d];
        __syncthreads();
        if (threadIdx.x >= d) s[threadIdx.x] += t;
        __syncthreads();
    }
    if (idx < n) {
        int off = bpre[blockIdx.x] + s[threadIdx.x] - dg;  // exclusive
        offs[idx] = off;
        cursor[idx] = off;
        dinv[idx] = rsqrtf((float)(dg + 1));  // +1 self-loop
    }
}

// ---------------- bucket edges by dst (1 edge/thread — measured best) ----------------
__global__ void k_bucket(const int* __restrict__ src, const int* __restrict__ dst,
                         int* cursor, int* __restrict__ bsrc, int E) {
    int e = blockIdx.x * blockDim.x + threadIdx.x;
    if (e >= E) return;
    int d = dst[e];
    int p = atomicAdd(&cursor[d], 1);
    bsrc[p] = src[e];
}

// ---------------- GEMM: out[n,NCOL] = act(X[n,128]) @ W[128,NCOL] (R2 exact) ----------------
template <int NCOL, bool RELU_IN>
__global__ __launch_bounds__(256) void k_gemm(const float* __restrict__ X,
                                              const float* __restrict__ W,
                                              float* __restrict__ out, int n) {
    constexpr int KT = 16;
    constexpr int COLG = NCOL / 4;
    constexpr int RTH = 256 / COLG;
    constexpr int RPT = 64 / RTH;
    __shared__ float Xs[KT][68];
    __shared__ float Ws[KT][NCOL];

    int tid = threadIdx.x;
    int row0 = blockIdx.x * 64;
    int cx = tid % COLG;
    int ry = tid / COLG;

    float4 acc[RPT];
#pragma unroll
    for (int j = 0; j < RPT; j++) acc[j] = make_float4(0.f, 0.f, 0.f, 0.f);

    for (int k0 = 0; k0 < 128; k0 += KT) {
        __syncthreads();
        {
            int rr = tid >> 2;
            int kv = (tid & 3) * 4;
            int row = row0 + rr;
            float4 v = make_float4(0.f, 0.f, 0.f, 0.f);
            if (row < n) v = __ldg(reinterpret_cast<const float4*>(X + row * 128 + k0 + kv));
            if (RELU_IN) {
                v.x = fmaxf(v.x, 0.f); v.y = fmaxf(v.y, 0.f);
                v.z = fmaxf(v.z, 0.f); v.w = fmaxf(v.w, 0.f);
            }
            Xs[kv + 0][rr] = v.x; Xs[kv + 1][rr] = v.y;
            Xs[kv + 2][rr] = v.z; Xs[kv + 3][rr] = v.w;
        }
#pragma unroll
        for (int lin = tid; lin < KT * COLG; lin += 256) {
            int kk = lin / COLG;
            int c = lin % COLG;
            *reinterpret_cast<float4*>(&Ws[kk][c * 4]) =
                __ldg(reinterpret_cast<const float4*>(W + (k0 + kk) * NCOL + c * 4));
        }
        __syncthreads();
#pragma unroll
        for (int kk = 0; kk < KT; kk++) {
            float4 w = *reinterpret_cast<float4*>(&Ws[kk][cx * 4]);
#pragma unroll
            for (int rv = 0; rv < RPT / 4; rv++) {
                float4 xr = *reinterpret_cast<float4*>(&Xs[kk][ry * RPT + rv * 4]);
                acc[rv * 4 + 0] = f4fma(w, xr.x, acc[rv * 4 + 0]);
                acc[rv * 4 + 1] = f4fma(w, xr.y, acc[rv * 4 + 1]);
                acc[rv * 4 + 2] = f4fma(w, xr.z, acc[rv * 4 + 2]);
                acc[rv * 4 + 3] = f4fma(w, xr.w, acc[rv * 4 + 3]);
            }
        }
    }
#pragma unroll
    for (int j = 0; j < RPT; j++) {
        int row = row0 + ry * RPT + j;
        if (row < n)
            *reinterpret_cast<float4*>(out + row * NCOL + cx * 4) = acc[j];
    }
}

// ---------------- gather aggregation, d=128 (R2 exact) ----------------
__global__ __launch_bounds__(256) void k_agg128(
    const float4* __restrict__ xw, const int* __restrict__ offs,
    const int* __restrict__ bsrc, const float* __restrict__ dinv,
    const float4* __restrict__ bias, float4* __restrict__ h, int n) {
    int t = blockIdx.x * blockDim.x + threadIdx.x;
    int node = t >> 5;
    int lane = t & 31;
    if (node >= n) return;
    float dn = __ldg(dinv + node);
    float4 bb = __ldg(bias + lane);
    float4 acc = f4fma(__ldg(xw + (size_t)node * 32 + lane), dn * dn, bb);
    int beg = __ldg(offs + node), end = __ldg(offs + node + 1);
    int j = beg;
    for (; j + 1 < end; j += 2) {
        int s0 = __ldg(bsrc + j), s1 = __ldg(bsrc + j + 1);
        float n0 = __ldg(dinv + s0) * dn, n1 = __ldg(dinv + s1) * dn;
        float4 v0 = __ldg(xw + (size_t)s0 * 32 + lane);
        float4 v1 = __ldg(xw + (size_t)s1 * 32 + lane);
        acc = f4fma(v0, n0, acc);
        acc = f4fma(v1, n1, acc);
    }
    if (j < end) {
        int s0 = __ldg(bsrc + j);
        acc = f4fma(__ldg(xw + (size_t)s0 * 32 + lane), __ldg(dinv + s0) * dn, acc);
    }
    h[(size_t)node * 32 + lane] = acc;
}

// ---------------- gather aggregation, d=64; fp16 output (only consumer is scorer) ----------------
__global__ __launch_bounds__(256) void k_agg64(
    const float2* __restrict__ xw, const int* __restrict__ offs,
    const int* __restrict__ bsrc, const float* __restrict__ dinv,
    const float2* __restrict__ bias, __half* __restrict__ h, int n) {
    int t = blockIdx.x * blockDim.x + threadIdx.x;
    int node = t >> 5;
    int lane = t & 31;
    if (node >= n) return;
    float dn = __ldg(dinv + node);
    float2 bb = __ldg(bias + lane);
    float2 v0 = __ldg(xw + (size_t)node * 32 + lane);
    float s = dn * dn;
    float2 acc = make_float2(v0.x * s + bb.x, v0.y * s + bb.y);
    int beg = __ldg(offs + node), end = __ldg(offs + node + 1);
    int j = beg;
    for (; j + 1 < end; j += 2) {
        int s0 = __ldg(bsrc + j), s1 = __ldg(bsrc + j + 1);
        float n0 = __ldg(dinv + s0) * dn, n1 = __ldg(dinv + s1) * dn;
        float2 a = __ldg(xw + (size_t)s0 * 32 + lane);
        float2 b = __ldg(xw + (size_t)s1 * 32 + lane);
        acc.x += a.x * n0 + b.x * n1;
        acc.y += a.y * n0 + b.y * n1;
    }
    if (j < end) {
        int s0 = __ldg(bsrc + j);
        float n0 = __ldg(dinv + s0) * dn;
        float2 a = __ldg(xw + (size_t)s0 * 32 + lane);
        acc.x += a.x * n0; acc.y += a.y * n0;
    }
    *reinterpret_cast<half2*>(h + (size_t)node * 64 + lane * 2) = __floats2half2_rn(acc.x, acc.y);
}

// ---------------- edge scorer: fp16 h2, 8 lanes/edge, 16B loads ----------------
__global__ __launch_bounds__(256) void k_score(const __half* __restrict__ h2,
                                               const int* __restrict__ src,
                                               const int* __restrict__ dst,
                                               float* __restrict__ out, int E) {
    int t = blockIdx.x * blockDim.x + threadIdx.x;
    int e = t >> 3;
    int lane = t & 7;
    if (e >= E) return;
    int s = __ldg(src + e);
    int d = __ldg(dst + e);
    uint4 pa = __ldg(reinterpret_cast<const uint4*>(h2 + (size_t)s * 64 + lane * 8));
    uint4 pb = __ldg(reinterpret_cast<const uint4*>(h2 + (size_t)d * 64 + lane * 8));
    float4 a0 = h4_to_f4(pa.x, pa.y);
    float4 a1 = h4_to_f4(pa.z, pa.w);
    float4 b0 = h4_to_f4(pb.x, pb.y);
    float4 b1 = h4_to_f4(pb.z, pb.w);
    float p = a0.x * b0.x + a0.y * b0.y + a0.z * b0.z + a0.w * b0.w
            + a1.x * b1.x + a1.y * b1.y + a1.z * b1.z + a1.w * b1.w;
#pragma unroll
    for (int off = 4; off; off >>= 1) p += __shfl_xor_sync(0xFFFFFFFFu, p, off);
    if (lane == 0) out[e] = p;
}

static inline int cdiv(long long a, int b) { return (int)((a + b - 1) / b); }

extern "C" void kernel_launch(void* const* d_in, const int* in_sizes, int n_in,
                              void* d_out, int out_size) {
    const float* x   = (const float*)d_in[0];
    const int*   src = (const int*)  d_in[1];
    const int*   dst = (const int*)  d_in[2];
    const float* W1  = (const float*)d_in[3];
    const float* b1  = (const float*)d_in[4];
    const float* W2  = (const float*)d_in[5];
    const float* b2  = (const float*)d_in[6];
    float* score = (float*)d_out;

    int n = in_sizes[0] / DINC;
    int E = in_sizes[1];
    int nb = cdiv(n, SCHUNK);

    void *p_deg, *p_dinv, *p_offs, *p_cursor, *p_bsrc, *p_bsum, *p_bpre,
         *p_xw1, *p_h1, *p_xw2, *p_h2;
    cudaGetSymbolAddress(&p_deg,    g_deg);
    cudaGetSymbolAddress(&p_dinv,   g_dinv);
    cudaGetSymbolAddress(&p_offs,   g_offs);
    cudaGetSymbolAddress(&p_cursor, g_cursor);
    cudaGetSymbolAddress(&p_bsrc,   g_bsrc);
    cudaGetSymbolAddress(&p_bsum,   g_bsum);
    cudaGetSymbolAddress(&p_bpre,   g_bpre);
    cudaGetSymbolAddress(&p_xw1,    g_xw1);
    cudaGetSymbolAddress(&p_h1,     g_h1);
    cudaGetSymbolAddress(&p_xw2,    g_xw2);
    cudaGetSymbolAddress(&p_h2,     g_h2h);
    int*    deg    = (int*)p_deg;
    float*  dinv   = (float*)p_dinv;
    int*    offs   = (int*)p_offs;
    int*    cursor = (int*)p_cursor;
    int*    bsrc   = (int*)p_bsrc;
    int*    bsum   = (int*)p_bsum;
    int*    bpre   = (int*)p_bpre;
    float*  xw1    = (float*)p_xw1;
    float*  h1     = (float*)p_h1;
    float*  xw2    = (float*)p_xw2;
    __half* h2     = (__half*)p_h2;

    // one-time host resources (no device allocation; streams/events only)
    static cudaStream_t s2 = nullptr;
    static cudaEvent_t evFork = nullptr, evJoin = nullptr;
    if (!s2) {
        cudaStreamCreateWithFlags(&s2, cudaStreamNonBlocking);
        cudaEventCreateWithFlags(&evFork, cudaEventDisableTiming);
        cudaEventCreateWithFlags(&evJoin, cudaEventDisableTiming);
    }

    const int B = 256;

    // ---- fork: GEMM1 (features only) on s2, CSR build (graph only) on capture stream ----
    cudaEventRecord(evFork, 0);
    cudaStreamWaitEvent(s2, evFork, 0);
    k_gemm<DHC, false><<<cdiv(n, 64), B, 0, s2>>>(x, W1, xw1, n);
    cudaEventRecord(evJoin, s2);

    // CSR build — parallel two-level scan
    cudaMemsetAsync(deg, 0, (size_t)n * sizeof(int));
    k_deg<<<cdiv(E, B), B>>>(dst, deg, E);
    k_scan_a<<<nb, SCHUNK>>>(deg, bsum, n);
    k_scan_b<<<1, 1024>>>(bsum, bpre, offs, nb, n);
    k_scan_c<<<nb, SCHUNK>>>(deg, bpre, offs, cursor, dinv, n);
    k_bucket<<<cdiv(E, B), B>>>(src, dst, cursor, bsrc, E);

    // ---- join: agg128 needs bucket (this stream) + gemm1 (s2) ----
    cudaStreamWaitEvent(0, evJoin, 0);
    k_agg128<<<cdiv((long long)n * 32, B), B>>>((const float4*)xw1, offs, bsrc, dinv,
                                                (const float4*)b1, (float4*)h1, n);

    // ---- layer 2 (relu fused into GEMM input; fp16 only at h2 output) ----
    k_gemm<DOUTC, true><<<cdiv(n, 64), B>>>(h1, W2, xw2, n);
    k_agg64<<<cdiv((long long)n * 32, B), B>>>((const float2*)xw2, offs, bsrc, dinv,
                                               (const float2*)b2, h2, n);

    // ---- edge scores (halved L2 gather traffic) ----
    k_score<<<cdiv((long long)E * 8, B), B>>>(h2, src, dst, score, E);
}

// round 15
// speedup vs baseline: 2.7869x; 1.0689x over previous
#include <cuda_runtime.h>
#include <cuda_fp16.h>

#define MAXN 50000
#define MAXE 800000
#define DINC 128
#define DHC  128
#define DOUTC 64
#define SCHUNK 256
#define MAXNB ((MAXN + SCHUNK - 1) / SCHUNK)

// ---- scratch (static device globals; no allocation allowed) ----
__device__ int    g_deg[MAXN];
__device__ float  g_dinv[MAXN];
__device__ int    g_offs[MAXN + 1];
__device__ int    g_cursor[MAXN];
__device__ int    g_bsrc[MAXE];
__device__ int    g_bsum[MAXNB];
__device__ int    g_bpre[MAXNB];
__device__ __half g_xw1h[MAXN * DHC];    // fp16: gathered by agg128 (410->205MB)
__device__ float  g_h1 [MAXN * DHC];     // fp32: dense-read by GEMM2 only
__device__ __half g_xw2h[MAXN * DOUTC];  // fp16: gathered by agg64
__device__ __half g_h2h[MAXN * DOUTC];   // fp16: gathered by scorer

// ---------------- small helpers ----------------
__device__ __forceinline__ float4 f4fma(float4 a, float s, float4 acc) {
    acc.x += a.x * s; acc.y += a.y * s; acc.z += a.z * s; acc.w += a.w * s;
    return acc;
}
__device__ __forceinline__ float4 h4_to_f4(unsigned lo_u, unsigned hi_u) {
    half2 lo = *reinterpret_cast<half2*>(&lo_u);
    half2 hi = *reinterpret_cast<half2*>(&hi_u);
    float2 a = __half22float2(lo), b = __half22float2(hi);
    return make_float4(a.x, a.y, b.x, b.y);
}
__device__ __forceinline__ uint2 f4_to_h4(float4 v) {
    half2 lo = __floats2half2_rn(v.x, v.y);
    half2 hi = __floats2half2_rn(v.z, v.w);
    uint2 p;
    p.x = *reinterpret_cast<unsigned*>(&lo);
    p.y = *reinterpret_cast<unsigned*>(&hi);
    return p;
}

// ---------------- degree (1 edge/thread — measured best) ----------------
__global__ void k_deg(const int* __restrict__ dst, int* deg, int E) {
    int e = blockIdx.x * blockDim.x + threadIdx.x;
    if (e < E) atomicAdd(&deg[dst[e]], 1);
}

// ---------------- two-level scan: A) per-block sums ----------------
__global__ void k_scan_a(const int* __restrict__ deg, int* __restrict__ bsum, int n) {
    __shared__ int s[SCHUNK];
    int idx = blockIdx.x * SCHUNK + threadIdx.x;
    s[threadIdx.x] = (idx < n) ? deg[idx] : 0;
    __syncthreads();
    for (int d = SCHUNK / 2; d > 0; d >>= 1) {
        if (threadIdx.x < d) s[threadIdx.x] += s[threadIdx.x + d];
        __syncthreads();
    }
    if (threadIdx.x == 0) bsum[blockIdx.x] = s[0];
}

// ---------------- B) single small block scans block sums; writes offs[n] ----------------
__global__ void k_scan_b(const int* __restrict__ bsum, int* __restrict__ bpre,
                         int* __restrict__ offs, int nb, int n) {
    const int T = 1024;
    __shared__ int s[T];
    int tid = threadIdx.x;
    int v = (tid < nb) ? bsum[tid] : 0;
    s[tid] = v;
    __syncthreads();
    for (int d = 1; d < T; d <<= 1) {
        int t = 0;
        if (tid >= d) t = s[tid - d];
        __syncthreads();
        if (tid >= d) s[tid] += t;
        __syncthreads();
    }
    if (tid < nb) bpre[tid] = s[tid] - v;   // exclusive prefix
    if (tid == T - 1) offs[n] = s[T - 1];   // total = E
}

// ---------------- C) per-chunk exclusive scan; writes offs, cursor, dinv ----------------
__global__ void k_scan_c(const int* __restrict__ deg, const int* __restrict__ bpre,
                         int* __restrict__ offs, int* __restrict__ cursor,
                         float* __restrict__ dinv, int n) {
    __shared__ int s[SCHUNK];
    int idx = blockIdx.x * SCHUNK + threadIdx.x;
    int dg = (idx < n) ? deg[idx] : 0;
    s[threadIdx.x] = dg;
    __syncthreads();
    for (int d = 1; d < SCHUNK; d <<= 1) {
        int t = 0;
        if (threadIdx.x >= d) t = s[threadIdx.x - d];
        __syncthreads();
        if (threadIdx.x >= d) s[threadIdx.x] += t;
        __syncthreads();
    }
    if (idx < n) {
        int off = bpre[blockIdx.x] + s[threadIdx.x] - dg;  // exclusive
        offs[idx] = off;
        cursor[idx] = off;
        dinv[idx] = rsqrtf((float)(dg + 1));  // +1 self-loop
    }
}

// ---------------- bucket edges by dst (1 edge/thread — measured best) ----------------
__global__ void k_bucket(const int* __restrict__ src, const int* __restrict__ dst,
                         int* cursor, int* __restrict__ bsrc, int E) {
    int e = blockIdx.x * blockDim.x + threadIdx.x;
    if (e >= E) return;
    int d = dst[e];
    int p = atomicAdd(&cursor[d], 1);
    bsrc[p] = src[e];
}

// ---------------- GEMM: out[n,NCOL] = act(X[n,128]) @ W[128,NCOL], fp16 epilogue ----------------
template <int NCOL, bool RELU_IN>
__global__ __launch_bounds__(256) void k_gemm(const float* __restrict__ X,
                                              const float* __restrict__ W,
                                              __half* __restrict__ out, int n) {
    constexpr int KT = 16;
    constexpr int COLG = NCOL / 4;
    constexpr int RTH = 256 / COLG;
    constexpr int RPT = 64 / RTH;
    __shared__ float Xs[KT][68];
    __shared__ float Ws[KT][NCOL];

    int tid = threadIdx.x;
    int row0 = blockIdx.x * 64;
    int cx = tid % COLG;
    int ry = tid / COLG;

    float4 acc[RPT];
#pragma unroll
    for (int j = 0; j < RPT; j++) acc[j] = make_float4(0.f, 0.f, 0.f, 0.f);

    for (int k0 = 0; k0 < 128; k0 += KT) {
        __syncthreads();
        {
            int rr = tid >> 2;
            int kv = (tid & 3) * 4;
            int row = row0 + rr;
            float4 v = make_float4(0.f, 0.f, 0.f, 0.f);
            if (row < n) v = __ldg(reinterpret_cast<const float4*>(X + row * 128 + k0 + kv));
            if (RELU_IN) {
                v.x = fmaxf(v.x, 0.f); v.y = fmaxf(v.y, 0.f);
                v.z = fmaxf(v.z, 0.f); v.w = fmaxf(v.w, 0.f);
            }
            Xs[kv + 0][rr] = v.x; Xs[kv + 1][rr] = v.y;
            Xs[kv + 2][rr] = v.z; Xs[kv + 3][rr] = v.w;
        }
#pragma unroll
        for (int lin = tid; lin < KT * COLG; lin += 256) {
            int kk = lin / COLG;
            int c = lin % COLG;
            *reinterpret_cast<float4*>(&Ws[kk][c * 4]) =
                __ldg(reinterpret_cast<const float4*>(W + (k0 + kk) * NCOL + c * 4));
        }
        __syncthreads();
#pragma unroll
        for (int kk = 0; kk < KT; kk++) {
            float4 w = *reinterpret_cast<float4*>(&Ws[kk][cx * 4]);
#pragma unroll
            for (int rv = 0; rv < RPT / 4; rv++) {
                float4 xr = *reinterpret_cast<float4*>(&Xs[kk][ry * RPT + rv * 4]);
                acc[rv * 4 + 0] = f4fma(w, xr.x, acc[rv * 4 + 0]);
                acc[rv * 4 + 1] = f4fma(w, xr.y, acc[rv * 4 + 1]);
                acc[rv * 4 + 2] = f4fma(w, xr.z, acc[rv * 4 + 2]);
                acc[rv * 4 + 3] = f4fma(w, xr.w, acc[rv * 4 + 3]);
            }
        }
    }
#pragma unroll
    for (int j = 0; j < RPT; j++) {
        int row = row0 + ry * RPT + j;
        if (row < n)
            *reinterpret_cast<uint2*>(out + (size_t)row * NCOL + cx * 4) = f4_to_h4(acc[j]);
    }
}

// ---------------- gather aggregation, d=128: fp16 gathers, fp32 accum, fp32 h1 out ----------------
__global__ __launch_bounds__(256) void k_agg128(
    const __half* __restrict__ xw, const int* __restrict__ offs,
    const int* __restrict__ bsrc, const float* __restrict__ dinv,
    const float4* __restrict__ bias, float4* __restrict__ h, int n) {
    int t = blockIdx.x * blockDim.x + threadIdx.x;
    int node = t >> 5;
    int lane = t & 31;
    if (node >= n) return;
    float dn = __ldg(dinv + node);
    float4 bb = __ldg(bias + lane);
    uint2 sp = __ldg(reinterpret_cast<const uint2*>(xw + (size_t)node * 128 + lane * 4));
    float4 acc = f4fma(h4_to_f4(sp.x, sp.y), dn * dn, bb);
    int beg = __ldg(offs + node), end = __ldg(offs + node + 1);
    int j = beg;
    for (; j + 1 < end; j += 2) {
        int s0 = __ldg(bsrc + j), s1 = __ldg(bsrc + j + 1);
        float n0 = __ldg(dinv + s0) * dn, n1 = __ldg(dinv + s1) * dn;
        uint2 p0 = __ldg(reinterpret_cast<const uint2*>(xw + (size_t)s0 * 128 + lane * 4));
        uint2 p1 = __ldg(reinterpret_cast<const uint2*>(xw + (size_t)s1 * 128 + lane * 4));
        acc = f4fma(h4_to_f4(p0.x, p0.y), n0, acc);
        acc = f4fma(h4_to_f4(p1.x, p1.y), n1, acc);
    }
    if (j < end) {
        int s0 = __ldg(bsrc + j);
        uint2 p0 = __ldg(reinterpret_cast<const uint2*>(xw + (size_t)s0 * 128 + lane * 4));
        acc = f4fma(h4_to_f4(p0.x, p0.y), __ldg(dinv + s0) * dn, acc);
    }
    h[(size_t)node * 32 + lane] = acc;
}

// ---------------- gather aggregation, d=64: fp16 gathers, fp32 accum, fp16 h2 out ----------------
__global__ __launch_bounds__(256) void k_agg64(
    const __half* __restrict__ xw, const int* __restrict__ offs,
    const int* __restrict__ bsrc, const float* __restrict__ dinv,
    const float2* __restrict__ bias, __half* __restrict__ h, int n) {
    int t = blockIdx.x * blockDim.x + threadIdx.x;
    int node = t >> 5;
    int lane = t & 31;
    if (node >= n) return;
    float dn = __ldg(dinv + node);
    float2 bb = __ldg(bias + lane);
    float2 sv = __half22float2(__ldg(reinterpret_cast<const half2*>(xw + (size_t)node * 64 + lane * 2)));
    float s = dn * dn;
    float2 acc = make_float2(sv.x * s + bb.x, sv.y * s + bb.y);
    int beg = __ldg(offs + node), end = __ldg(offs + node + 1);
    int j = beg;
    for (; j + 1 < end; j += 2) {
        int s0 = __ldg(bsrc + j), s1 = __ldg(bsrc + j + 1);
        float n0 = __ldg(dinv + s0) * dn, n1 = __ldg(dinv + s1) * dn;
        float2 a = __half22float2(__ldg(reinterpret_cast<const half2*>(xw + (size_t)s0 * 64 + lane * 2)));
        float2 b = __half22float2(__ldg(reinterpret_cast<const half2*>(xw + (size_t)s1 * 64 + lane * 2)));
        acc.x += a.x * n0 + b.x * n1;
        acc.y += a.y * n0 + b.y * n1;
    }
    if (j < end) {
        int s0 = __ldg(bsrc + j);
        float n0 = __ldg(dinv + s0) * dn;
        float2 a = __half22float2(__ldg(reinterpret_cast<const half2*>(xw + (size_t)s0 * 64 + lane * 2)));
        acc.x += a.x * n0; acc.y += a.y * n0;
    }
    *reinterpret_cast<half2*>(h + (size_t)node * 64 + lane * 2) = __floats2half2_rn(acc.x, acc.y);
}

// ---------------- edge scorer: fp16 h2, 8 lanes/edge, 16B loads (measured best) ----------------
__global__ __launch_bounds__(256) void k_score(const __half* __restrict__ h2,
                                               const int* __restrict__ src,
                                               const int* __restrict__ dst,
                                               float* __restrict__ out, int E) {
    int t = blockIdx.x * blockDim.x + threadIdx.x;
    int e = t >> 3;
    int lane = t & 7;
    if (e >= E) return;
    int s = __ldg(src + e);
    int d = __ldg(dst + e);
    uint4 pa = __ldg(reinterpret_cast<const uint4*>(h2 + (size_t)s * 64 + lane * 8));
    uint4 pb = __ldg(reinterpret_cast<const uint4*>(h2 + (size_t)d * 64 + lane * 8));
    float4 a0 = h4_to_f4(pa.x, pa.y);
    float4 a1 = h4_to_f4(pa.z, pa.w);
    float4 b0 = h4_to_f4(pb.x, pb.y);
    float4 b1 = h4_to_f4(pb.z, pb.w);
    float p = a0.x * b0.x + a0.y * b0.y + a0.z * b0.z + a0.w * b0.w
            + a1.x * b1.x + a1.y * b1.y + a1.z * b1.z + a1.w * b1.w;
#pragma unroll
    for (int off = 4; off; off >>= 1) p += __shfl_xor_sync(0xFFFFFFFFu, p, off);
    if (lane == 0) out[e] = p;
}

static inline int cdiv(long long a, int b) { return (int)((a + b - 1) / b); }

extern "C" void kernel_launch(void* const* d_in, const int* in_sizes, int n_in,
                              void* d_out, int out_size) {
    const float* x   = (const float*)d_in[0];
    const int*   src = (const int*)  d_in[1];
    const int*   dst = (const int*)  d_in[2];
    const float* W1  = (const float*)d_in[3];
    const float* b1  = (const float*)d_in[4];
    const float* W2  = (const float*)d_in[5];
    const float* b2  = (const float*)d_in[6];
    float* score = (float*)d_out;

    int n = in_sizes[0] / DINC;
    int E = in_sizes[1];
    int nb = cdiv(n, SCHUNK);

    void *p_deg, *p_dinv, *p_offs, *p_cursor, *p_bsrc, *p_bsum, *p_bpre,
         *p_xw1, *p_h1, *p_xw2, *p_h2;
    cudaGetSymbolAddress(&p_deg,    g_deg);
    cudaGetSymbolAddress(&p_dinv,   g_dinv);
    cudaGetSymbolAddress(&p_offs,   g_offs);
    cudaGetSymbolAddress(&p_cursor, g_cursor);
    cudaGetSymbolAddress(&p_bsrc,   g_bsrc);
    cudaGetSymbolAddress(&p_bsum,   g_bsum);
    cudaGetSymbolAddress(&p_bpre,   g_bpre);
    cudaGetSymbolAddress(&p_xw1,    g_xw1h);
    cudaGetSymbolAddress(&p_h1,     g_h1);
    cudaGetSymbolAddress(&p_xw2,    g_xw2h);
    cudaGetSymbolAddress(&p_h2,     g_h2h);
    int*    deg    = (int*)p_deg;
    float*  dinv   = (float*)p_dinv;
    int*    offs   = (int*)p_offs;
    int*    cursor = (int*)p_cursor;
    int*    bsrc   = (int*)p_bsrc;
    int*    bsum   = (int*)p_bsum;
    int*    bpre   = (int*)p_bpre;
    __half* xw1    = (__half*)p_xw1;
    float*  h1     = (float*)p_h1;
    __half* xw2    = (__half*)p_xw2;
    __half* h2     = (__half*)p_h2;

    // one-time host resources (no device allocation; streams/events only)
    static cudaStream_t s2 = nullptr;
    static cudaEvent_t evFork = nullptr, evJoin = nullptr;
    if (!s2) {
        cudaStreamCreateWithFlags(&s2, cudaStreamNonBlocking);
        cudaEventCreateWithFlags(&evFork, cudaEventDisableTiming);
        cudaEventCreateWithFlags(&evJoin, cudaEventDisableTiming);
    }

    const int B = 256;

    // ---- fork: GEMM1 (features only) on s2, CSR build (graph only) on capture stream ----
    cudaEventRecord(evFork, 0);
    cudaStreamWaitEvent(s2, evFork, 0);
    k_gemm<DHC, false><<<cdiv(n, 64), B, 0, s2>>>(x, W1, xw1, n);
    cudaEventRecord(evJoin, s2);

    // CSR build — parallel two-level scan
    cudaMemsetAsync(deg, 0, (size_t)n * sizeof(int));
    k_deg<<<cdiv(E, B), B>>>(dst, deg, E);
    k_scan_a<<<nb, SCHUNK>>>(deg, bsum, n);
    k_scan_b<<<1, 1024>>>(bsum, bpre, offs, nb, n);
    k_scan_c<<<nb, SCHUNK>>>(deg, bpre, offs, cursor, dinv, n);
    k_bucket<<<cdiv(E, B), B>>>(src, dst, cursor, bsrc, E);

    // ---- join: agg128 needs bucket (this stream) + gemm1 (s2) ----
    cudaStreamWaitEvent(0, evJoin, 0);
    k_agg128<<<cdiv((long long)n * 32, B), B>>>(xw1, offs, bsrc, dinv,
                                                (const float4*)b1, (float4*)h1, n);

    // ---- layer 2 (relu fused into GEMM input; fp16 intermediates) ----
    k_gemm<DOUTC, true><<<cdiv(n, 64), B>>>(h1, W2, xw2, n);
    k_agg64<<<cdiv((long long)n * 32, B), B>>>(xw2, offs, bsrc, dinv,
                                               (const float2*)b2, h2, n);

    // ---- edge scores ----
    k_score<<<cdiv((long long)E * 8, B), B>>>(h2, src, dst, score, E);
}